// round 5
// baseline (speedup 1.0000x reference)
#include <cuda_runtime.h>
#include <cuda_bf16.h>

// Problem constants
#define MROWS  32768      // B*N
#define DDIM   1024
#define NHEAD  16
#define CHUNK  128
#define HDIM   64
#define NCHUNK 64         // N / CHUNK
#define SEQ    8192
#define NBH    64         // B*H

// Scratch (static __device__ allocations — allowed; no cudaMalloc anywhere)
__device__ float g_q[MROWS * DDIM];
__device__ float g_k[MROWS * DDIM];
__device__ float g_v[MROWS * DDIM];
__device__ float g_o[MROWS * DDIM];
__device__ float g_lf[NBH * SEQ];
__device__ float g_dS[NBH * NCHUNK * HDIM * HDIM];
__device__ float g_Sin[NBH * NCHUNK * HDIM * HDIM];

// ---------------------------------------------------------------------------
// SGEMM: C[m,n] = act( sum_k A[m,k] * W[n,k] )   (A: [M,1024], W: [1024,1024])
// 128x128 tile, BK=8, 256 threads, 8x8 per-thread register tile, reg prefetch.
// act: 0 = none, 1 = silu
// ---------------------------------------------------------------------------
__global__ __launch_bounds__(256) void sgemm_act_kernel(
    const float* __restrict__ A, const float* __restrict__ W,
    float* __restrict__ C, int act)
{
    __shared__ float As[8][128];
    __shared__ float Bs[8][128];
    const int K = DDIM;
    int tid = threadIdx.x;
    int tx = tid & 15, ty = tid >> 4;
    int row0 = blockIdx.y * 128, col0 = blockIdx.x * 128;

    int lr = tid >> 1;           // 0..127
    int lk = (tid & 1) * 4;      // 0 or 4
    const float* Ap = A + (size_t)(row0 + lr) * K + lk;
    const float* Wp = W + (size_t)(col0 + lr) * K + lk;

    float acc[8][8];
#pragma unroll
    for (int i = 0; i < 8; i++)
#pragma unroll
        for (int j = 0; j < 8; j++) acc[i][j] = 0.f;

    float4 a4 = *(const float4*)(Ap);
    float4 b4 = *(const float4*)(Wp);

    for (int k0 = 0; k0 < K; k0 += 8) {
        As[lk + 0][lr] = a4.x; As[lk + 1][lr] = a4.y;
        As[lk + 2][lr] = a4.z; As[lk + 3][lr] = a4.w;
        Bs[lk + 0][lr] = b4.x; Bs[lk + 1][lr] = b4.y;
        Bs[lk + 2][lr] = b4.z; Bs[lk + 3][lr] = b4.w;
        __syncthreads();
        if (k0 + 8 < K) {
            a4 = *(const float4*)(Ap + k0 + 8);
            b4 = *(const float4*)(Wp + k0 + 8);
        }
#pragma unroll
        for (int kk = 0; kk < 8; kk++) {
            float4 a0 = *(const float4*)&As[kk][ty * 8];
            float4 a1 = *(const float4*)&As[kk][ty * 8 + 4];
            float4 b0 = *(const float4*)&Bs[kk][tx * 8];
            float4 b1 = *(const float4*)&Bs[kk][tx * 8 + 4];
            float ar[8] = {a0.x, a0.y, a0.z, a0.w, a1.x, a1.y, a1.z, a1.w};
            float br[8] = {b0.x, b0.y, b0.z, b0.w, b1.x, b1.y, b1.z, b1.w};
#pragma unroll
            for (int i = 0; i < 8; i++)
#pragma unroll
                for (int j = 0; j < 8; j++) acc[i][j] += ar[i] * br[j];
        }
        __syncthreads();
    }

#pragma unroll
    for (int i = 0; i < 8; i++) {
        size_t r = (size_t)(row0 + ty * 8 + i);
        float* Crow = C + r * DDIM + col0 + tx * 8;
        float t[8];
#pragma unroll
        for (int j = 0; j < 8; j++) {
            float vv = acc[i][j];
            if (act) vv = vv / (1.f + expf(-vv));   // silu
            t[j] = vv;
        }
        *(float4*)(Crow)     = make_float4(t[0], t[1], t[2], t[3]);
        *(float4*)(Crow + 4) = make_float4(t[4], t[5], t[6], t[7]);
    }
}

// ---------------------------------------------------------------------------
// Forget gate: lf[b,h,n] = log_sigmoid( x[row] . Wf[h] + delta[h] )
// One block per token row, 128 threads (4 warps x 4 heads each).
// ---------------------------------------------------------------------------
__global__ void fgate_kernel(const float* __restrict__ x, const float* __restrict__ Wf,
                             const float* __restrict__ delta, float* __restrict__ lf)
{
    __shared__ float sx[1024];
    int row = blockIdx.x;
    int tid = threadIdx.x;
    for (int i = tid; i < 1024; i += 128) sx[i] = x[(size_t)row * 1024 + i];
    __syncthreads();
    int warp = tid >> 5, lane = tid & 31;
    for (int h = warp; h < NHEAD; h += 4) {
        float s = 0.f;
        const float* wf = Wf + h * 1024;
        for (int kk = lane; kk < 1024; kk += 32) s += sx[kk] * wf[kk];
#pragma unroll
        for (int off = 16; off; off >>= 1) s += __shfl_xor_sync(0xffffffffu, s, off);
        if (lane == 0) {
            float z = s + delta[h];
            float ls = fminf(z, 0.f) - log1pf(expf(-fabsf(z)));
            int b = row >> 13, n = row & 8191;
            lf[((size_t)(b * NHEAD + h)) * SEQ + n] = ls;
        }
    }
}

// ---------------------------------------------------------------------------
// Pass A (parallel over all chunks): per (chunk, b, h)
//  - in-place inclusive cumsum of lf within the chunk (written back)
//  - A[i][j] = (q_i.k_j) * exp(l_i - l_j) for j<=i
//  - o_intra = A @ v  (written to g_o, overwrite)
//  - dS[d][e] = sum_j k[j][d]*exp(L - l_j)*v[j][e]
// ---------------------------------------------------------------------------
__global__ void scan_intra_kernel(const float* __restrict__ q, const float* __restrict__ k,
                                  const float* __restrict__ v, float* __restrict__ lf,
                                  float* __restrict__ o, float* __restrict__ dS)
{
    extern __shared__ float sh[];
    float* sq  = sh;                 // 128*65
    float* sk  = sq  + 128 * 65;     // 128*65
    float* sv  = sk  + 128 * 65;     // 128*65
    float* sA  = sv  + 128 * 65;     // 128*129
    float* slf = sA  + 128 * 129;    // 128
    float* sE  = slf + 128;          // 128  exp(l)
    float* sEi = sE  + 128;          // 128  exp(-l)

    int chunk = blockIdx.x, bh = blockIdx.y;
    int b = bh >> 4, h = bh & 15;
    int tid = threadIdx.x;
    size_t base = ((size_t)(b * SEQ + chunk * CHUNK)) * DDIM + h * HDIM;

    for (int idx = tid; idx < CHUNK * HDIM; idx += 256) {
        int r = idx >> 6, c = idx & 63;
        size_t g = base + (size_t)r * DDIM + c;
        sq[r * 65 + c] = q[g];
        sk[r * 65 + c] = k[g];
        sv[r * 65 + c] = v[g];
    }
    size_t lfbase = (size_t)bh * SEQ + (size_t)chunk * CHUNK;
    if (tid < 128) slf[tid] = lf[lfbase + tid];
    __syncthreads();

    // inclusive scan (Hillis-Steele) of slf[0..127]
    for (int off = 1; off < 128; off <<= 1) {
        float add = 0.f;
        if (tid < 128 && tid >= off) add = slf[tid - off];
        __syncthreads();
        if (tid < 128) slf[tid] += add;
        __syncthreads();
    }
    if (tid < 128) {
        float l = slf[tid];
        lf[lfbase + tid] = l;        // cumsum written back for passes B/C
        sE[tid]  = expf(l);
        sEi[tid] = expf(-l);
    }
    __syncthreads();

    int tx = tid & 15, ty = tid >> 4;

    // ---- A = (q k^T) with decay+mask ----
    {
        int i0 = ty * 8, j0 = tx * 8;
        float acc[8][8];
#pragma unroll
        for (int i = 0; i < 8; i++)
#pragma unroll
            for (int j = 0; j < 8; j++) acc[i][j] = 0.f;
        for (int d = 0; d < HDIM; d++) {
            float qr[8], kr[8];
#pragma unroll
            for (int i = 0; i < 8; i++) qr[i] = sq[(i0 + i) * 65 + d];
#pragma unroll
            for (int j = 0; j < 8; j++) kr[j] = sk[(j0 + j) * 65 + d];
#pragma unroll
            for (int i = 0; i < 8; i++)
#pragma unroll
                for (int j = 0; j < 8; j++) acc[i][j] += qr[i] * kr[j];
        }
#pragma unroll
        for (int i = 0; i < 8; i++) {
            float ei = sE[i0 + i];
#pragma unroll
            for (int j = 0; j < 8; j++) {
                float val = (j0 + j <= i0 + i) ? acc[i][j] * ei * sEi[j0 + j] : 0.f;
                sA[(i0 + i) * 129 + (j0 + j)] = val;
            }
        }
    }
    __syncthreads();

    // scale k rows by exp(L - l_j)
    float eL = sE[127];
    for (int idx = tid; idx < CHUNK * HDIM; idx += 256) {
        int r = idx >> 6, c = idx & 63;
        sk[r * 65 + c] *= eL * sEi[r];
    }
    __syncthreads();

    // ---- o_intra = A @ v   (128x64, per thread 8 rows x 4 cols) ----
    {
        int i0 = ty * 8, d0 = tx * 4;
        float acc[8][4];
#pragma unroll
        for (int i = 0; i < 8; i++)
#pragma unroll
            for (int d = 0; d < 4; d++) acc[i][d] = 0.f;
        for (int j = 0; j < CHUNK; j++) {
            float vr[4];
#pragma unroll
            for (int d = 0; d < 4; d++) vr[d] = sv[j * 65 + d0 + d];
#pragma unroll
            for (int i = 0; i < 8; i++) {
                float a = sA[(i0 + i) * 129 + j];
#pragma unroll
                for (int d = 0; d < 4; d++) acc[i][d] += a * vr[d];
            }
        }
#pragma unroll
        for (int i = 0; i < 8; i++)
#pragma unroll
            for (int d = 0; d < 4; d++)
                o[base + (size_t)(i0 + i) * DDIM + d0 + d] = acc[i][d];
    }

    // ---- dS[d][e] = sum_j kd[j][d] * v[j][e]   (64x64, per thread 4x4) ----
    {
        int d0 = ty * 4, e0 = tx * 4;
        float acc[4][4];
#pragma unroll
        for (int a = 0; a < 4; a++)
#pragma unroll
            for (int e = 0; e < 4; e++) acc[a][e] = 0.f;
        for (int j = 0; j < CHUNK; j++) {
            float kr[4], vr[4];
#pragma unroll
            for (int a = 0; a < 4; a++) kr[a] = sk[j * 65 + d0 + a];
#pragma unroll
            for (int e = 0; e < 4; e++) vr[e] = sv[j * 65 + e0 + e];
#pragma unroll
            for (int a = 0; a < 4; a++)
#pragma unroll
                for (int e = 0; e < 4; e++) acc[a][e] += kr[a] * vr[e];
        }
        size_t sb = ((size_t)bh * NCHUNK + chunk) * (HDIM * HDIM);
#pragma unroll
        for (int a = 0; a < 4; a++)
#pragma unroll
            for (int e = 0; e < 4; e++)
                dS[sb + (size_t)(d0 + a) * HDIM + e0 + e] = acc[a][e];
    }
}

// ---------------------------------------------------------------------------
// Pass B (sequential over chunks, parallel over 64 (b,h)):
//   S_in[chunk] = S;  S = exp(L_chunk)*S + dS[chunk]
// ---------------------------------------------------------------------------
__global__ void scan_state_kernel(const float* __restrict__ dS, const float* __restrict__ lf,
                                  float* __restrict__ Sin)
{
    int bh = blockIdx.x, tid = threadIdx.x;
    float S[16];
#pragma unroll
    for (int j = 0; j < 16; j++) S[j] = 0.f;
    for (int chunk = 0; chunk < NCHUNK; chunk++) {
        size_t base = ((size_t)bh * NCHUNK + chunk) * (HDIM * HDIM);
        float eL = expf(lf[(size_t)bh * SEQ + chunk * CHUNK + (CHUNK - 1)]);
#pragma unroll
        for (int j = 0; j < 16; j++) {
            int idx = tid + j * 256;
            Sin[base + idx] = S[j];
            S[j] = eL * S[j] + dS[base + idx];
        }
    }
}

// ---------------------------------------------------------------------------
// Pass C (parallel over all chunks): o += exp(l_i) * (q @ S_in)
// ---------------------------------------------------------------------------
__global__ void scan_inter_kernel(const float* __restrict__ q, const float* __restrict__ lf,
                                  const float* __restrict__ Sin, float* __restrict__ o)
{
    extern __shared__ float sh[];
    float* sq  = sh;               // 128*65
    float* sS  = sq + 128 * 65;    // 64*65
    float* slf = sS + 64 * 65;     // 128
    int chunk = blockIdx.x, bh = blockIdx.y;
    int b = bh >> 4, h = bh & 15;
    int tid = threadIdx.x;
    size_t base = ((size_t)(b * SEQ + chunk * CHUNK)) * DDIM + h * HDIM;

    for (int idx = tid; idx < CHUNK * HDIM; idx += 256) {
        int r = idx >> 6, c = idx & 63;
        sq[r * 65 + c] = q[base + (size_t)r * DDIM + c];
    }
    size_t sb = ((size_t)bh * NCHUNK + chunk) * (HDIM * HDIM);
    for (int idx = tid; idx < HDIM * HDIM; idx += 256)
        sS[(idx >> 6) * 65 + (idx & 63)] = Sin[sb + idx];
    if (tid < 128) slf[tid] = lf[(size_t)bh * SEQ + chunk * CHUNK + tid];
    __syncthreads();

    int tx = tid & 15, ty = tid >> 4;
    int i0 = ty * 8, d0 = tx * 4;
    float acc[8][4];
#pragma unroll
    for (int i = 0; i < 8; i++)
#pragma unroll
        for (int d = 0; d < 4; d++) acc[i][d] = 0.f;
    for (int e = 0; e < HDIM; e++) {
        float sr[4];
#pragma unroll
        for (int d = 0; d < 4; d++) sr[d] = sS[e * 65 + d0 + d];
#pragma unroll
        for (int i = 0; i < 8; i++) {
            float qv = sq[(i0 + i) * 65 + e];
#pragma unroll
            for (int d = 0; d < 4; d++) acc[i][d] += qv * sr[d];
        }
    }
#pragma unroll
    for (int i = 0; i < 8; i++) {
        float ei = expf(slf[i0 + i]);
#pragma unroll
        for (int d = 0; d < 4; d++) {
            size_t g = base + (size_t)(i0 + i) * DDIM + d0 + d;
            o[g] += ei * acc[i][d];
        }
    }
}

// ---------------------------------------------------------------------------
// RMSNorm in place over last dim (1024), with weight.
// ---------------------------------------------------------------------------
__global__ void rmsnorm_kernel(float* __restrict__ o, const float* __restrict__ w)
{
    __shared__ float red[8];
    size_t base = (size_t)blockIdx.x * 1024;
    int tid = threadIdx.x;
    float vals[4];
    float ss = 0.f;
#pragma unroll
    for (int j = 0; j < 4; j++) {
        float t = o[base + tid + j * 256];
        vals[j] = t;
        ss += t * t;
    }
#pragma unroll
    for (int off = 16; off; off >>= 1) ss += __shfl_xor_sync(0xffffffffu, ss, off);
    if ((tid & 31) == 0) red[tid >> 5] = ss;
    __syncthreads();
    float tot = red[0] + red[1] + red[2] + red[3] + red[4] + red[5] + red[6] + red[7];
    float scale = rsqrtf(tot * (1.f / 1024.f) + 1e-6f);
#pragma unroll
    for (int j = 0; j < 4; j++) {
        int c = tid + j * 256;
        o[base + c] = vals[j] * scale * w[c];
    }
}

// ---------------------------------------------------------------------------
extern "C" void kernel_launch(void* const* d_in, const int* in_sizes, int n_in,
                              void* d_out, int out_size)
{
    const float* x  = (const float*)d_in[0];
    const float* Wq = (const float*)d_in[1];
    const float* Wk = (const float*)d_in[2];
    const float* Wv = (const float*)d_in[3];
    const float* Wo = (const float*)d_in[4];
    const float* Wf = (const float*)d_in[5];
    const float* dl = (const float*)d_in[6];
    const float* nw = (const float*)d_in[7];
    float* out = (float*)d_out;

    float *q, *k, *v, *o, *lf, *dS, *Sin;
    cudaGetSymbolAddress((void**)&q,   g_q);
    cudaGetSymbolAddress((void**)&k,   g_k);
    cudaGetSymbolAddress((void**)&v,   g_v);
    cudaGetSymbolAddress((void**)&o,   g_o);
    cudaGetSymbolAddress((void**)&lf,  g_lf);
    cudaGetSymbolAddress((void**)&dS,  g_dS);
    cudaGetSymbolAddress((void**)&Sin, g_Sin);

    const int SMEM_INTRA = (3 * 128 * 65 + 128 * 129 + 3 * 128) * 4;  // 167424 B
    const int SMEM_INTER = (128 * 65 + 64 * 65 + 128) * 4;            // 50432 B
    cudaFuncSetAttribute(scan_intra_kernel, cudaFuncAttributeMaxDynamicSharedMemorySize, SMEM_INTRA);
    cudaFuncSetAttribute(scan_inter_kernel, cudaFuncAttributeMaxDynamicSharedMemorySize, SMEM_INTER);

    dim3 gg(DDIM / 128, MROWS / 128);   // (8, 256)

    sgemm_act_kernel<<<gg, 256>>>(x, Wq, q, 1);
    sgemm_act_kernel<<<gg, 256>>>(x, Wk, k, 1);
    sgemm_act_kernel<<<gg, 256>>>(x, Wv, v, 0);
    fgate_kernel<<<MROWS, 128>>>(x, Wf, dl, lf);
    scan_intra_kernel<<<dim3(NCHUNK, NBH), 256, SMEM_INTRA>>>(q, k, v, lf, o, dS);
    scan_state_kernel<<<NBH, 256>>>(dS, lf, Sin);
    scan_inter_kernel<<<dim3(NCHUNK, NBH), 256, SMEM_INTER>>>(q, lf, Sin, o);
    rmsnorm_kernel<<<MROWS, 256>>>(o, nw);
    sgemm_act_kernel<<<gg, 256>>>(o, Wo, out, 0);
}

// round 9
// speedup vs baseline: 1.6570x; 1.6570x over previous
#include <cuda_runtime.h>
#include <cuda_bf16.h>
#include <cstdint>

// Problem constants
#define MROWS  32768      // B*N
#define DDIM   1024
#define NHEAD  16
#define CHUNK  128
#define HDIM   64
#define NCHUNK 64         // N / CHUNK
#define SEQ    8192
#define NBH    64         // B*H

// GEMM tiling (mma.sync bf16)
#define GTM 128
#define GTN 128
#define GBK 32
#define PITCH 80          // smem row pitch in bytes (32 bf16 = 64B data + 16B pad)
#define NSTAGE 96         // 3 passes * (1024/32)

// ---------------------------------------------------------------------------
// Scratch (static __device__ allocations — no cudaMalloc anywhere)
// ---------------------------------------------------------------------------
__device__ float g_q[MROWS * DDIM];
__device__ float g_k[MROWS * DDIM];
__device__ float g_v[MROWS * DDIM];
__device__ float g_o[MROWS * DDIM];
__device__ float g_lf[NBH * SEQ];
__device__ float g_dS[NBH * NCHUNK * HDIM * HDIM];
__device__ float g_Sin[NBH * NCHUNK * HDIM * HDIM];

__device__ __nv_bfloat16 g_xhi[MROWS * DDIM];
__device__ __nv_bfloat16 g_xlo[MROWS * DDIM];
__device__ __nv_bfloat16 g_ohi[MROWS * DDIM];
__device__ __nv_bfloat16 g_olo[MROWS * DDIM];
__device__ __nv_bfloat16 g_wqhi[DDIM * DDIM];
__device__ __nv_bfloat16 g_wqlo[DDIM * DDIM];
__device__ __nv_bfloat16 g_wkhi[DDIM * DDIM];
__device__ __nv_bfloat16 g_wklo[DDIM * DDIM];
__device__ __nv_bfloat16 g_wvhi[DDIM * DDIM];
__device__ __nv_bfloat16 g_wvlo[DDIM * DDIM];
__device__ __nv_bfloat16 g_wohi[DDIM * DDIM];
__device__ __nv_bfloat16 g_wolo[DDIM * DDIM];

// ---------------------------------------------------------------------------
// PTX helpers (all plain sm_80-era instructions — no 'a'-gated features)
// ---------------------------------------------------------------------------
static __device__ __forceinline__ uint32_t smem_u32(const void* p) {
    uint32_t a;
    asm("{ .reg .u64 t; cvta.to.shared.u64 t, %1; cvt.u32.u64 %0, t; }" : "=r"(a) : "l"(p));
    return a;
}
static __device__ __forceinline__ void cp16(uint32_t dst, const void* src) {
    asm volatile("cp.async.cg.shared.global [%0], [%1], 16;" :: "r"(dst), "l"(src));
}
static __device__ __forceinline__ void ldsm4(uint32_t* r, uint32_t addr) {
    asm volatile("ldmatrix.sync.aligned.m8n8.x4.shared.b16 {%0,%1,%2,%3}, [%4];"
                 : "=r"(r[0]), "=r"(r[1]), "=r"(r[2]), "=r"(r[3]) : "r"(addr));
}
static __device__ __forceinline__ void mma16816(float* d, const uint32_t* a,
                                                uint32_t b0, uint32_t b1) {
    asm volatile(
        "mma.sync.aligned.m16n8k16.row.col.f32.bf16.bf16.f32 "
        "{%0,%1,%2,%3}, {%4,%5,%6,%7}, {%8,%9}, {%0,%1,%2,%3};"
        : "+f"(d[0]), "+f"(d[1]), "+f"(d[2]), "+f"(d[3])
        : "r"(a[0]), "r"(a[1]), "r"(a[2]), "r"(a[3]), "r"(b0), "r"(b1));
}

// ---------------------------------------------------------------------------
// Split fp32 -> (hi, lo) bf16 pair.
// ---------------------------------------------------------------------------
__global__ void split_kernel(const float* __restrict__ src, __nv_bfloat16* __restrict__ hi,
                             __nv_bfloat16* __restrict__ lo, int n4)
{
    int i = blockIdx.x * blockDim.x + threadIdx.x;
    if (i >= n4) return;
    float4 v = ((const float4*)src)[i];
    __nv_bfloat16 h0 = __float2bfloat16(v.x), h1 = __float2bfloat16(v.y),
                  h2 = __float2bfloat16(v.z), h3 = __float2bfloat16(v.w);
    __nv_bfloat16 l0 = __float2bfloat16(v.x - __bfloat162float(h0));
    __nv_bfloat16 l1 = __float2bfloat16(v.y - __bfloat162float(h1));
    __nv_bfloat16 l2 = __float2bfloat16(v.z - __bfloat162float(h2));
    __nv_bfloat16 l3 = __float2bfloat16(v.w - __bfloat162float(h3));
    __nv_bfloat162* h2p = (__nv_bfloat162*)hi;
    __nv_bfloat162* l2p = (__nv_bfloat162*)lo;
    h2p[2 * i]     = __halves2bfloat162(h0, h1);
    h2p[2 * i + 1] = __halves2bfloat162(h2, h3);
    l2p[2 * i]     = __halves2bfloat162(l0, l1);
    l2p[2 * i + 1] = __halves2bfloat162(l2, l3);
}

// ---------------------------------------------------------------------------
// mma.sync bf16 split GEMM: C[m,n] = act( A[m,:] . W[n,:] ), A,W row-major K-contig.
//   A ≈ Ahi+Alo, W ≈ Bhi+Blo; acc = hi*hi + hi*lo + lo*hi in fp32 regs.
// CTA tile 128x128, 8 warps (64x32 each), BK=32, cp.async double buffer.
// ---------------------------------------------------------------------------
__global__ __launch_bounds__(256, 2) void gemm_mma(
    const __nv_bfloat16* __restrict__ Ahi, const __nv_bfloat16* __restrict__ Alo,
    const __nv_bfloat16* __restrict__ Bhi, const __nv_bfloat16* __restrict__ Blo,
    float* __restrict__ C, int act)
{
    __shared__ __align__(16) char smem[4 * GTM * PITCH];  // A0, B0, A1, B1 (10240B each)
    const uint32_t sb = smem_u32(smem);
    const uint32_t aoff[2] = {sb, sb + 2u * GTM * PITCH};
    const uint32_t boff[2] = {sb + 1u * GTM * PITCH, sb + 3u * GTM * PITCH};

    const int tid = threadIdx.x, lane = tid & 31, wid = tid >> 5;
    const int wm = wid & 1, wn = wid >> 1;                 // warp: rows wm*64, cols wn*32
    const int row0 = blockIdx.y * GTM, col0 = blockIdx.x * GTN;

    const char* Aps[3] = {(const char*)Ahi, (const char*)Ahi, (const char*)Alo};
    const char* Bps[3] = {(const char*)Bhi, (const char*)Blo, (const char*)Bhi};

    // cp.async task map: 512 16B-chunks per tile; thread does 2 A + 2 B chunks.
    const int r0t = tid >> 2, c0t = tid & 3;               // task tid
    const int r1t = (tid + 256) >> 2, c1t = tid & 3;       // task tid+256

#define PREFETCH(S, BUF)                                                          \
    do {                                                                          \
        int pass = (S) >> 5, kk = ((S) & 31) * GBK;                               \
        const char* Abase = Aps[pass];                                            \
        const char* Bbase = Bps[pass];                                            \
        cp16(aoff[BUF] + r0t * PITCH + c0t * 16,                                  \
             Abase + ((size_t)(row0 + r0t) * DDIM + kk) * 2 + c0t * 16);          \
        cp16(aoff[BUF] + r1t * PITCH + c1t * 16,                                  \
             Abase + ((size_t)(row0 + r1t) * DDIM + kk) * 2 + c1t * 16);          \
        cp16(boff[BUF] + r0t * PITCH + c0t * 16,                                  \
             Bbase + ((size_t)(col0 + r0t) * DDIM + kk) * 2 + c0t * 16);          \
        cp16(boff[BUF] + r1t * PITCH + c1t * 16,                                  \
             Bbase + ((size_t)(col0 + r1t) * DDIM + kk) * 2 + c1t * 16);          \
        asm volatile("cp.async.commit_group;" ::: "memory");                      \
    } while (0)

    float acc[4][4][4];
#pragma unroll
    for (int mf = 0; mf < 4; mf++)
#pragma unroll
        for (int nf = 0; nf < 4; nf++)
#pragma unroll
            for (int e = 0; e < 4; e++) acc[mf][nf][e] = 0.f;

    // ldmatrix per-lane address offset (same pattern for A and B tiles):
    // matrices: {rows0-7,k0}, {rows8-15,k0}, {rows0-7,k0+8}, {rows8-15,k0+8}
    const int lrow = ((lane >> 3) & 1) * 8 + (lane & 7);
    const int lcol8 = (lane >> 4) * 8;

    PREFETCH(0, 0);
    PREFETCH(1, 1);

    for (int s = 0; s < NSTAGE; s++) {
        if (s < NSTAGE - 1) asm volatile("cp.async.wait_group 1;" ::: "memory");
        else                asm volatile("cp.async.wait_group 0;" ::: "memory");
        __syncthreads();

        const int buf = s & 1;
        const uint32_t abase = aoff[buf] + (wm * 64) * PITCH;
        const uint32_t bbase = boff[buf] + (wn * 32) * PITCH;
#pragma unroll
        for (int ks = 0; ks < GBK; ks += 16) {
            const uint32_t loff = (uint32_t)lrow * PITCH + (uint32_t)(ks + lcol8) * 2;
            uint32_t af[4][4];
#pragma unroll
            for (int mf = 0; mf < 4; mf++)
                ldsm4(af[mf], abase + mf * 16 * PITCH + loff);
            uint32_t breg[4][2];
#pragma unroll
            for (int p = 0; p < 2; p++) {
                uint32_t t[4];
                ldsm4(t, bbase + p * 16 * PITCH + loff);
                breg[2 * p + 0][0] = t[0]; breg[2 * p + 0][1] = t[2];
                breg[2 * p + 1][0] = t[1]; breg[2 * p + 1][1] = t[3];
            }
#pragma unroll
            for (int mf = 0; mf < 4; mf++)
#pragma unroll
                for (int nf = 0; nf < 4; nf++)
                    mma16816(acc[mf][nf], af[mf], breg[nf][0], breg[nf][1]);
        }
        __syncthreads();
        if (s + 2 < NSTAGE) PREFETCH(s + 2, buf);
    }
#undef PREFETCH

    // Epilogue: d0,d1 -> (row, col..col+1); d2,d3 -> (row+8, col..col+1)
    const int erow = row0 + wm * 64 + (lane >> 2);
    const int ecol = col0 + wn * 32 + (lane & 3) * 2;
#pragma unroll
    for (int mf = 0; mf < 4; mf++) {
#pragma unroll
        for (int nf = 0; nf < 4; nf++) {
            float t0 = acc[mf][nf][0], t1 = acc[mf][nf][1];
            float t2 = acc[mf][nf][2], t3 = acc[mf][nf][3];
            if (act) {
                t0 = t0 / (1.f + expf(-t0));
                t1 = t1 / (1.f + expf(-t1));
                t2 = t2 / (1.f + expf(-t2));
                t3 = t3 / (1.f + expf(-t3));
            }
            size_t g0 = (size_t)(erow + mf * 16) * DDIM + ecol + nf * 8;
            size_t g1 = (size_t)(erow + mf * 16 + 8) * DDIM + ecol + nf * 8;
            *(float2*)(C + g0) = make_float2(t0, t1);
            *(float2*)(C + g1) = make_float2(t2, t3);
        }
    }
}

// ---------------------------------------------------------------------------
// Forget gate: lf[b,h,n] = log_sigmoid( x[row] . Wf[h] + delta[h] )
// ---------------------------------------------------------------------------
__global__ void fgate_kernel(const float* __restrict__ x, const float* __restrict__ Wf,
                             const float* __restrict__ delta, float* __restrict__ lf)
{
    __shared__ float sx[1024];
    int row = blockIdx.x;
    int tid = threadIdx.x;
    for (int i = tid; i < 1024; i += 128) sx[i] = x[(size_t)row * 1024 + i];
    __syncthreads();
    int warp = tid >> 5, lane = tid & 31;
    for (int h = warp; h < NHEAD; h += 4) {
        float s = 0.f;
        const float* wf = Wf + h * 1024;
        for (int kk = lane; kk < 1024; kk += 32) s += sx[kk] * wf[kk];
#pragma unroll
        for (int off = 16; off; off >>= 1) s += __shfl_xor_sync(0xffffffffu, s, off);
        if (lane == 0) {
            float z = s + delta[h];
            float ls = fminf(z, 0.f) - log1pf(expf(-fabsf(z)));
            int b = row >> 13, n = row & 8191;
            lf[((size_t)(b * NHEAD + h)) * SEQ + n] = ls;
        }
    }
}

// ---------------------------------------------------------------------------
// Pass A (parallel over all chunks): cumsum gates, intra-chunk output, dS.
// ---------------------------------------------------------------------------
__global__ void scan_intra_kernel(const float* __restrict__ q, const float* __restrict__ k,
                                  const float* __restrict__ v, float* __restrict__ lf,
                                  float* __restrict__ o, float* __restrict__ dS)
{
    extern __shared__ float sh[];
    float* sq  = sh;
    float* sk  = sq  + 128 * 65;
    float* sv  = sk  + 128 * 65;
    float* sA  = sv  + 128 * 65;
    float* slf = sA  + 128 * 129;
    float* sE  = slf + 128;
    float* sEi = sE  + 128;

    int chunk = blockIdx.x, bh = blockIdx.y;
    int b = bh >> 4, h = bh & 15;
    int tid = threadIdx.x;
    size_t base = ((size_t)(b * SEQ + chunk * CHUNK)) * DDIM + h * HDIM;

    for (int idx = tid; idx < CHUNK * HDIM; idx += 256) {
        int r = idx >> 6, c = idx & 63;
        size_t g = base + (size_t)r * DDIM + c;
        sq[r * 65 + c] = q[g];
        sk[r * 65 + c] = k[g];
        sv[r * 65 + c] = v[g];
    }
    size_t lfbase = (size_t)bh * SEQ + (size_t)chunk * CHUNK;
    if (tid < 128) slf[tid] = lf[lfbase + tid];
    __syncthreads();

    for (int off = 1; off < 128; off <<= 1) {
        float add = 0.f;
        if (tid < 128 && tid >= off) add = slf[tid - off];
        __syncthreads();
        if (tid < 128) slf[tid] += add;
        __syncthreads();
    }
    if (tid < 128) {
        float l = slf[tid];
        lf[lfbase + tid] = l;
        sE[tid]  = expf(l);
        sEi[tid] = expf(-l);
    }
    __syncthreads();

    int tx = tid & 15, ty = tid >> 4;

    {   // A = (q k^T) * decay, masked
        int i0 = ty * 8, j0 = tx * 8;
        float acc[8][8];
#pragma unroll
        for (int i = 0; i < 8; i++)
#pragma unroll
            for (int j = 0; j < 8; j++) acc[i][j] = 0.f;
        for (int d = 0; d < HDIM; d++) {
            float qr[8], kr[8];
#pragma unroll
            for (int i = 0; i < 8; i++) qr[i] = sq[(i0 + i) * 65 + d];
#pragma unroll
            for (int j = 0; j < 8; j++) kr[j] = sk[(j0 + j) * 65 + d];
#pragma unroll
            for (int i = 0; i < 8; i++)
#pragma unroll
                for (int j = 0; j < 8; j++) acc[i][j] += qr[i] * kr[j];
        }
#pragma unroll
        for (int i = 0; i < 8; i++) {
            float ei = sE[i0 + i];
#pragma unroll
            for (int j = 0; j < 8; j++) {
                float val = (j0 + j <= i0 + i) ? acc[i][j] * ei * sEi[j0 + j] : 0.f;
                sA[(i0 + i) * 129 + (j0 + j)] = val;
            }
        }
    }
    __syncthreads();

    float eL = sE[127];
    for (int idx = tid; idx < CHUNK * HDIM; idx += 256) {
        int r = idx >> 6, c = idx & 63;
        sk[r * 65 + c] *= eL * sEi[r];
    }
    __syncthreads();

    {   // o_intra = A @ v
        int i0 = ty * 8, d0 = tx * 4;
        float acc[8][4];
#pragma unroll
        for (int i = 0; i < 8; i++)
#pragma unroll
            for (int d = 0; d < 4; d++) acc[i][d] = 0.f;
        for (int j = 0; j < CHUNK; j++) {
            float vr[4];
#pragma unroll
            for (int d = 0; d < 4; d++) vr[d] = sv[j * 65 + d0 + d];
#pragma unroll
            for (int i = 0; i < 8; i++) {
                float a = sA[(i0 + i) * 129 + j];
#pragma unroll
                for (int d = 0; d < 4; d++) acc[i][d] += a * vr[d];
            }
        }
#pragma unroll
        for (int i = 0; i < 8; i++)
#pragma unroll
            for (int d = 0; d < 4; d++)
                o[base + (size_t)(i0 + i) * DDIM + d0 + d] = acc[i][d];
    }

    {   // dS = kd^T @ v
        int d0 = ty * 4, e0 = tx * 4;
        float acc[4][4];
#pragma unroll
        for (int a = 0; a < 4; a++)
#pragma unroll
            for (int e = 0; e < 4; e++) acc[a][e] = 0.f;
        for (int j = 0; j < CHUNK; j++) {
            float kr[4], vr[4];
#pragma unroll
            for (int a = 0; a < 4; a++) kr[a] = sk[j * 65 + d0 + a];
#pragma unroll
            for (int e = 0; e < 4; e++) vr[e] = sv[j * 65 + e0 + e];
#pragma unroll
            for (int a = 0; a < 4; a++)
#pragma unroll
                for (int e = 0; e < 4; e++) acc[a][e] += kr[a] * vr[e];
        }
        size_t sb2 = ((size_t)bh * NCHUNK + chunk) * (HDIM * HDIM);
#pragma unroll
        for (int a = 0; a < 4; a++)
#pragma unroll
            for (int e = 0; e < 4; e++)
                dS[sb2 + (size_t)(d0 + a) * HDIM + e0 + e] = acc[a][e];
    }
}

// ---------------------------------------------------------------------------
// Pass B: sequential 64-step state scan over 64x64 matrices, per (b,h).
// ---------------------------------------------------------------------------
__global__ void scan_state_kernel(const float* __restrict__ dS, const float* __restrict__ lf,
                                  float* __restrict__ Sin)
{
    int bh = blockIdx.x, tid = threadIdx.x;
    float S[16];
#pragma unroll
    for (int j = 0; j < 16; j++) S[j] = 0.f;
    for (int chunk = 0; chunk < NCHUNK; chunk++) {
        size_t base = ((size_t)bh * NCHUNK + chunk) * (HDIM * HDIM);
        float eL = expf(lf[(size_t)bh * SEQ + chunk * CHUNK + (CHUNK - 1)]);
#pragma unroll
        for (int j = 0; j < 16; j++) {
            int idx = tid + j * 256;
            Sin[base + idx] = S[j];
            S[j] = eL * S[j] + dS[base + idx];
        }
    }
}

// ---------------------------------------------------------------------------
// Pass C: o += exp(l_i) * (q @ S_in)
// ---------------------------------------------------------------------------
__global__ void scan_inter_kernel(const float* __restrict__ q, const float* __restrict__ lf,
                                  const float* __restrict__ Sin, float* __restrict__ o)
{
    extern __shared__ float sh[];
    float* sq  = sh;
    float* sS  = sq + 128 * 65;
    float* slf = sS + 64 * 65;
    int chunk = blockIdx.x, bh = blockIdx.y;
    int b = bh >> 4, h = bh & 15;
    int tid = threadIdx.x;
    size_t base = ((size_t)(b * SEQ + chunk * CHUNK)) * DDIM + h * HDIM;

    for (int idx = tid; idx < CHUNK * HDIM; idx += 256) {
        int r = idx >> 6, c = idx & 63;
        sq[r * 65 + c] = q[base + (size_t)r * DDIM + c];
    }
    size_t sb2 = ((size_t)bh * NCHUNK + chunk) * (HDIM * HDIM);
    for (int idx = tid; idx < HDIM * HDIM; idx += 256)
        sS[(idx >> 6) * 65 + (idx & 63)] = Sin[sb2 + idx];
    if (tid < 128) slf[tid] = lf[(size_t)bh * SEQ + chunk * CHUNK + tid];
    __syncthreads();

    int tx = tid & 15, ty = tid >> 4;
    int i0 = ty * 8, d0 = tx * 4;
    float acc[8][4];
#pragma unroll
    for (int i = 0; i < 8; i++)
#pragma unroll
        for (int d = 0; d < 4; d++) acc[i][d] = 0.f;
    for (int e = 0; e < HDIM; e++) {
        float sr[4];
#pragma unroll
        for (int d = 0; d < 4; d++) sr[d] = sS[e * 65 + d0 + d];
#pragma unroll
        for (int i = 0; i < 8; i++) {
            float qv = sq[(i0 + i) * 65 + e];
#pragma unroll
            for (int d = 0; d < 4; d++) acc[i][d] += qv * sr[d];
        }
    }
#pragma unroll
    for (int i = 0; i < 8; i++) {
        float ei = expf(slf[i0 + i]);
#pragma unroll
        for (int d = 0; d < 4; d++) {
            size_t g = base + (size_t)(i0 + i) * DDIM + d0 + d;
            o[g] += ei * acc[i][d];
        }
    }
}

// ---------------------------------------------------------------------------
// RMSNorm in place over last dim (1024), with weight.
// ---------------------------------------------------------------------------
__global__ void rmsnorm_kernel(float* __restrict__ o, const float* __restrict__ w)
{
    __shared__ float red[8];
    size_t base = (size_t)blockIdx.x * 1024;
    int tid = threadIdx.x;
    float vals[4];
    float ss = 0.f;
#pragma unroll
    for (int j = 0; j < 4; j++) {
        float t = o[base + tid + j * 256];
        vals[j] = t;
        ss += t * t;
    }
#pragma unroll
    for (int off = 16; off; off >>= 1) ss += __shfl_xor_sync(0xffffffffu, ss, off);
    if ((tid & 31) == 0) red[tid >> 5] = ss;
    __syncthreads();
    float tot = red[0] + red[1] + red[2] + red[3] + red[4] + red[5] + red[6] + red[7];
    float scale = rsqrtf(tot * (1.f / 1024.f) + 1e-6f);
#pragma unroll
    for (int j = 0; j < 4; j++) {
        int c = tid + j * 256;
        o[base + c] = vals[j] * scale * w[c];
    }
}

// ---------------------------------------------------------------------------
extern "C" void kernel_launch(void* const* d_in, const int* in_sizes, int n_in,
                              void* d_out, int out_size)
{
    const float* x  = (const float*)d_in[0];
    const float* Wq = (const float*)d_in[1];
    const float* Wk = (const float*)d_in[2];
    const float* Wv = (const float*)d_in[3];
    const float* Wo = (const float*)d_in[4];
    const float* Wf = (const float*)d_in[5];
    const float* dl = (const float*)d_in[6];
    const float* nw = (const float*)d_in[7];
    float* out = (float*)d_out;

    float *q, *k, *v, *o, *lf, *dS, *Sin;
    cudaGetSymbolAddress((void**)&q,   g_q);
    cudaGetSymbolAddress((void**)&k,   g_k);
    cudaGetSymbolAddress((void**)&v,   g_v);
    cudaGetSymbolAddress((void**)&o,   g_o);
    cudaGetSymbolAddress((void**)&lf,  g_lf);
    cudaGetSymbolAddress((void**)&dS,  g_dS);
    cudaGetSymbolAddress((void**)&Sin, g_Sin);

    __nv_bfloat16 *xhi, *xlo, *ohi, *olo;
    __nv_bfloat16 *wqh, *wql, *wkh, *wkl, *wvh, *wvl, *woh, *wol;
    cudaGetSymbolAddress((void**)&xhi, g_xhi);
    cudaGetSymbolAddress((void**)&xlo, g_xlo);
    cudaGetSymbolAddress((void**)&ohi, g_ohi);
    cudaGetSymbolAddress((void**)&olo, g_olo);
    cudaGetSymbolAddress((void**)&wqh, g_wqhi);
    cudaGetSymbolAddress((void**)&wql, g_wqlo);
    cudaGetSymbolAddress((void**)&wkh, g_wkhi);
    cudaGetSymbolAddress((void**)&wkl, g_wklo);
    cudaGetSymbolAddress((void**)&wvh, g_wvhi);
    cudaGetSymbolAddress((void**)&wvl, g_wvlo);
    cudaGetSymbolAddress((void**)&woh, g_wohi);
    cudaGetSymbolAddress((void**)&wol, g_wolo);

    const int SMEM_INTRA = (3 * 128 * 65 + 128 * 129 + 3 * 128) * 4;  // 167424 B
    const int SMEM_INTER = (128 * 65 + 64 * 65 + 128) * 4;            // 50432 B
    cudaFuncSetAttribute(scan_intra_kernel, cudaFuncAttributeMaxDynamicSharedMemorySize, SMEM_INTRA);
    cudaFuncSetAttribute(scan_inter_kernel, cudaFuncAttributeMaxDynamicSharedMemorySize, SMEM_INTER);

    const int N4X = MROWS * DDIM / 4;
    const int N4W = DDIM * DDIM / 4;

    // Split inputs / weights into bf16 (hi, lo)
    split_kernel<<<N4X / 256, 256>>>(x, xhi, xlo, N4X);
    split_kernel<<<N4W / 256, 256>>>(Wq, wqh, wql, N4W);
    split_kernel<<<N4W / 256, 256>>>(Wk, wkh, wkl, N4W);
    split_kernel<<<N4W / 256, 256>>>(Wv, wvh, wvl, N4W);
    split_kernel<<<N4W / 256, 256>>>(Wo, woh, wol, N4W);

    fgate_kernel<<<MROWS, 128>>>(x, Wf, dl, lf);

    dim3 gg(DDIM / GTN, MROWS / GTM);   // (8, 256)
    gemm_mma<<<gg, 256>>>(xhi, xlo, wqh, wql, q, 1);
    gemm_mma<<<gg, 256>>>(xhi, xlo, wkh, wkl, k, 1);
    gemm_mma<<<gg, 256>>>(xhi, xlo, wvh, wvl, v, 0);

    scan_intra_kernel<<<dim3(NCHUNK, NBH), 256, SMEM_INTRA>>>(q, k, v, lf, o, dS);
    scan_state_kernel<<<NBH, 256>>>(dS, lf, Sin);
    scan_inter_kernel<<<dim3(NCHUNK, NBH), 256, SMEM_INTER>>>(q, lf, Sin, o);
    rmsnorm_kernel<<<MROWS, 256>>>(o, nw);

    split_kernel<<<N4X / 256, 256>>>(o, ohi, olo, N4X);
    gemm_mma<<<gg, 256>>>(ohi, olo, woh, wol, out, 0);
}

// round 11
// speedup vs baseline: 1.9680x; 1.1877x over previous
#include <cuda_runtime.h>
#include <cuda_bf16.h>
#include <cstdint>

// Problem constants
#define MROWS  32768      // B*N
#define DDIM   1024
#define NHEAD  16
#define CHUNK  128
#define HDIM   64
#define NCHUNK 64         // N / CHUNK
#define SEQ    8192
#define NBH    64         // B*H

// GEMM tiling (mma.sync bf16, fused hi/lo)
#define GTM 128
#define GTN 128
#define GBK 32
#define PITCH 80          // smem row pitch in bytes (32 bf16 = 64B data + 16B pad)
#define NSTAGE 32         // 1024 / 32
#define TILEB (GTM * PITCH)          // 10240 B per tile
#define BUFB  (4 * TILEB)            // Ahi, Alo, Bhi, Blo per buffer

// ---------------------------------------------------------------------------
// Scratch (static __device__ allocations — no cudaMalloc anywhere)
// ---------------------------------------------------------------------------
__device__ float g_q[MROWS * DDIM];
__device__ float g_k[MROWS * DDIM];
__device__ float g_v[MROWS * DDIM];
__device__ float g_o[MROWS * DDIM];
__device__ float g_lf[NBH * SEQ];
__device__ float g_dS[NBH * NCHUNK * HDIM * HDIM];
__device__ float g_Sin[NBH * NCHUNK * HDIM * HDIM];

__device__ __nv_bfloat16 g_xhi[MROWS * DDIM];
__device__ __nv_bfloat16 g_xlo[MROWS * DDIM];
__device__ __nv_bfloat16 g_ohi[MROWS * DDIM];
__device__ __nv_bfloat16 g_olo[MROWS * DDIM];
__device__ __nv_bfloat16 g_wqhi[DDIM * DDIM];
__device__ __nv_bfloat16 g_wqlo[DDIM * DDIM];
__device__ __nv_bfloat16 g_wkhi[DDIM * DDIM];
__device__ __nv_bfloat16 g_wklo[DDIM * DDIM];
__device__ __nv_bfloat16 g_wvhi[DDIM * DDIM];
__device__ __nv_bfloat16 g_wvlo[DDIM * DDIM];
__device__ __nv_bfloat16 g_wohi[DDIM * DDIM];
__device__ __nv_bfloat16 g_wolo[DDIM * DDIM];

// ---------------------------------------------------------------------------
// PTX helpers (plain sm_80-era instructions only — nothing 'a'-gated)
// ---------------------------------------------------------------------------
static __device__ __forceinline__ uint32_t smem_u32(const void* p) {
    uint32_t a;
    asm("{ .reg .u64 t; cvta.to.shared.u64 t, %1; cvt.u32.u64 %0, t; }" : "=r"(a) : "l"(p));
    return a;
}
static __device__ __forceinline__ void cp16(uint32_t dst, const void* src) {
    asm volatile("cp.async.cg.shared.global [%0], [%1], 16;" :: "r"(dst), "l"(src));
}
static __device__ __forceinline__ void ldsm4(uint32_t* r, uint32_t addr) {
    asm volatile("ldmatrix.sync.aligned.m8n8.x4.shared.b16 {%0,%1,%2,%3}, [%4];"
                 : "=r"(r[0]), "=r"(r[1]), "=r"(r[2]), "=r"(r[3]) : "r"(addr));
}
static __device__ __forceinline__ void mma16816(float* d, const uint32_t* a,
                                                uint32_t b0, uint32_t b1) {
    asm volatile(
        "mma.sync.aligned.m16n8k16.row.col.f32.bf16.bf16.f32 "
        "{%0,%1,%2,%3}, {%4,%5,%6,%7}, {%8,%9}, {%0,%1,%2,%3};"
        : "+f"(d[0]), "+f"(d[1]), "+f"(d[2]), "+f"(d[3])
        : "r"(a[0]), "r"(a[1]), "r"(a[2]), "r"(a[3]), "r"(b0), "r"(b1));
}

// ---------------------------------------------------------------------------
// Split fp32 -> (hi, lo) bf16 pair (used for the 4 weight matrices only).
// ---------------------------------------------------------------------------
__global__ void split_kernel(const float* __restrict__ src, __nv_bfloat16* __restrict__ hi,
                             __nv_bfloat16* __restrict__ lo, int n4)
{
    int i = blockIdx.x * blockDim.x + threadIdx.x;
    if (i >= n4) return;
    float4 v = ((const float4*)src)[i];
    __nv_bfloat16 h0 = __float2bfloat16(v.x), h1 = __float2bfloat16(v.y),
                  h2 = __float2bfloat16(v.z), h3 = __float2bfloat16(v.w);
    __nv_bfloat16 l0 = __float2bfloat16(v.x - __bfloat162float(h0));
    __nv_bfloat16 l1 = __float2bfloat16(v.y - __bfloat162float(h1));
    __nv_bfloat16 l2 = __float2bfloat16(v.z - __bfloat162float(h2));
    __nv_bfloat16 l3 = __float2bfloat16(v.w - __bfloat162float(h3));
    __nv_bfloat162* h2p = (__nv_bfloat162*)hi;
    __nv_bfloat162* l2p = (__nv_bfloat162*)lo;
    h2p[2 * i]     = __halves2bfloat162(h0, h1);
    h2p[2 * i + 1] = __halves2bfloat162(h2, h3);
    l2p[2 * i]     = __halves2bfloat162(l0, l1);
    l2p[2 * i + 1] = __halves2bfloat162(l2, l3);
}

// ---------------------------------------------------------------------------
// Fused-pass mma.sync bf16 split GEMM: C = act( (Ahi+Alo) . (Bhi+Blo)^T )
//   per K-stage load all 4 tiles once, issue hi*hi + hi*lo + lo*hi.
// CTA tile 128x128, 8 warps (64x32 each), BK=32, cp.async double buffer.
// ---------------------------------------------------------------------------
__global__ __launch_bounds__(256, 2) void gemm_mma(
    const __nv_bfloat16* __restrict__ Ahi, const __nv_bfloat16* __restrict__ Alo,
    const __nv_bfloat16* __restrict__ Bhi, const __nv_bfloat16* __restrict__ Blo,
    float* __restrict__ C, int act)
{
    extern __shared__ __align__(16) char smem[];   // 2 * BUFB = 81920 B
    const uint32_t sb = smem_u32(smem);

    const int tid = threadIdx.x, lane = tid & 31, wid = tid >> 5;
    const int wm = wid & 1, wn = wid >> 1;                 // warp: rows wm*64, cols wn*32
    const int row0 = blockIdx.y * GTM, col0 = blockIdx.x * GTN;

    // cp.async task map: 512 16B-chunks per tile; thread does chunks tid, tid+256.
    const int r0t = tid >> 2, c0t = (tid & 3) * 16;
    const int r1t = (tid + 256) >> 2;

#define PREFETCH(S, BUF)                                                            \
    do {                                                                            \
        int kk = (S) * GBK;                                                         \
        uint32_t bufb = sb + (uint32_t)(BUF) * BUFB;                                \
        const char* s0 = (const char*)Ahi + ((size_t)(row0) * DDIM + kk) * 2;       \
        const char* s1 = (const char*)Alo + ((size_t)(row0) * DDIM + kk) * 2;       \
        const char* s2 = (const char*)Bhi + ((size_t)(col0) * DDIM + kk) * 2;       \
        const char* s3 = (const char*)Blo + ((size_t)(col0) * DDIM + kk) * 2;       \
        cp16(bufb + 0 * TILEB + r0t * PITCH + c0t, s0 + (size_t)r0t * 2048 + c0t);  \
        cp16(bufb + 0 * TILEB + r1t * PITCH + c0t, s0 + (size_t)r1t * 2048 + c0t);  \
        cp16(bufb + 1 * TILEB + r0t * PITCH + c0t, s1 + (size_t)r0t * 2048 + c0t);  \
        cp16(bufb + 1 * TILEB + r1t * PITCH + c0t, s1 + (size_t)r1t * 2048 + c0t);  \
        cp16(bufb + 2 * TILEB + r0t * PITCH + c0t, s2 + (size_t)r0t * 2048 + c0t);  \
        cp16(bufb + 2 * TILEB + r1t * PITCH + c0t, s2 + (size_t)r1t * 2048 + c0t);  \
        cp16(bufb + 3 * TILEB + r0t * PITCH + c0t, s3 + (size_t)r0t * 2048 + c0t);  \
        cp16(bufb + 3 * TILEB + r1t * PITCH + c0t, s3 + (size_t)r1t * 2048 + c0t);  \
        asm volatile("cp.async.commit_group;" ::: "memory");                        \
    } while (0)

    float acc[4][4][4];
#pragma unroll
    for (int mf = 0; mf < 4; mf++)
#pragma unroll
        for (int nf = 0; nf < 4; nf++)
#pragma unroll
            for (int e = 0; e < 4; e++) acc[mf][nf][e] = 0.f;

    // ldmatrix per-lane address offset (same pattern for A and B tiles)
    const int lrow = ((lane >> 3) & 1) * 8 + (lane & 7);
    const int lcol8 = (lane >> 4) * 8;

    PREFETCH(0, 0);
    PREFETCH(1, 1);

    for (int s = 0; s < NSTAGE; s++) {
        if (s < NSTAGE - 1) asm volatile("cp.async.wait_group 1;" ::: "memory");
        else                asm volatile("cp.async.wait_group 0;" ::: "memory");
        __syncthreads();

        const uint32_t bufb = sb + (uint32_t)(s & 1) * BUFB;
        const uint32_t aho = bufb + 0 * TILEB + (wm * 64) * PITCH;
        const uint32_t alo = bufb + 1 * TILEB + (wm * 64) * PITCH;
        const uint32_t bho = bufb + 2 * TILEB + (wn * 32) * PITCH;
        const uint32_t blo = bufb + 3 * TILEB + (wn * 32) * PITCH;
#pragma unroll
        for (int ks = 0; ks < GBK; ks += 16) {
            const uint32_t loff = (uint32_t)lrow * PITCH + (uint32_t)(ks + lcol8) * 2;
            uint32_t af[4][4];
            uint32_t bh[4][2], bl[4][2];
#pragma unroll
            for (int mf = 0; mf < 4; mf++)
                ldsm4(af[mf], aho + mf * 16 * PITCH + loff);
#pragma unroll
            for (int p = 0; p < 2; p++) {
                uint32_t t[4];
                ldsm4(t, bho + p * 16 * PITCH + loff);
                bh[2 * p + 0][0] = t[0]; bh[2 * p + 0][1] = t[2];
                bh[2 * p + 1][0] = t[1]; bh[2 * p + 1][1] = t[3];
            }
#pragma unroll
            for (int mf = 0; mf < 4; mf++)
#pragma unroll
                for (int nf = 0; nf < 4; nf++)
                    mma16816(acc[mf][nf], af[mf], bh[nf][0], bh[nf][1]);   // hi*hi
#pragma unroll
            for (int p = 0; p < 2; p++) {
                uint32_t t[4];
                ldsm4(t, blo + p * 16 * PITCH + loff);
                bl[2 * p + 0][0] = t[0]; bl[2 * p + 0][1] = t[2];
                bl[2 * p + 1][0] = t[1]; bl[2 * p + 1][1] = t[3];
            }
#pragma unroll
            for (int mf = 0; mf < 4; mf++)
#pragma unroll
                for (int nf = 0; nf < 4; nf++)
                    mma16816(acc[mf][nf], af[mf], bl[nf][0], bl[nf][1]);   // hi*lo
#pragma unroll
            for (int mf = 0; mf < 4; mf++)
                ldsm4(af[mf], alo + mf * 16 * PITCH + loff);               // reuse af
#pragma unroll
            for (int mf = 0; mf < 4; mf++)
#pragma unroll
                for (int nf = 0; nf < 4; nf++)
                    mma16816(acc[mf][nf], af[mf], bh[nf][0], bh[nf][1]);   // lo*hi
        }
        __syncthreads();
        if (s + 2 < NSTAGE) PREFETCH(s + 2, s & 1);
    }
#undef PREFETCH

    // Epilogue
    const int erow = row0 + wm * 64 + (lane >> 2);
    const int ecol = col0 + wn * 32 + (lane & 3) * 2;
#pragma unroll
    for (int mf = 0; mf < 4; mf++) {
#pragma unroll
        for (int nf = 0; nf < 4; nf++) {
            float t0 = acc[mf][nf][0], t1 = acc[mf][nf][1];
            float t2 = acc[mf][nf][2], t3 = acc[mf][nf][3];
            if (act) {
                t0 = t0 / (1.f + expf(-t0));
                t1 = t1 / (1.f + expf(-t1));
                t2 = t2 / (1.f + expf(-t2));
                t3 = t3 / (1.f + expf(-t3));
            }
            size_t g0 = (size_t)(erow + mf * 16) * DDIM + ecol + nf * 8;
            size_t g1 = (size_t)(erow + mf * 16 + 8) * DDIM + ecol + nf * 8;
            *(float2*)(C + g0) = make_float2(t0, t1);
            *(float2*)(C + g1) = make_float2(t2, t3);
        }
    }
}

// ---------------------------------------------------------------------------
// fgate2 + x-split fusion: Wf staged once per block (16x1024 in 64KB smem),
// 8 rows per block, one warp per row (row held in registers). Also emits
// xhi/xlo for its 8 rows (saves the separate big split pass).
// ---------------------------------------------------------------------------
__global__ __launch_bounds__(256) void fgate2_kernel(
    const float* __restrict__ x, const float* __restrict__ Wf,
    const float* __restrict__ delta, float* __restrict__ lf,
    __nv_bfloat16* __restrict__ xhi, __nv_bfloat16* __restrict__ xlo)
{
    extern __shared__ float sw[];  // 16*1024 floats = 64KB
    int tid = threadIdx.x, lane = tid & 31, warp = tid >> 5;
    for (int i = tid; i < 4096; i += 256)
        ((float4*)sw)[i] = ((const float4*)Wf)[i];
    __syncthreads();

    int row = blockIdx.x * 8 + warp;
    const float4* xp = (const float4*)(x + (size_t)row * 1024);
    float4 xr[8];
#pragma unroll
    for (int j = 0; j < 8; j++) xr[j] = xp[lane + 32 * j];

    // emit xhi / xlo for this row
    __nv_bfloat162* xh2 = (__nv_bfloat162*)(xhi + (size_t)row * 1024);
    __nv_bfloat162* xl2 = (__nv_bfloat162*)(xlo + (size_t)row * 1024);
#pragma unroll
    for (int j = 0; j < 8; j++) {
        int c2 = (lane + 32 * j) * 2;  // bf16x2 index
        __nv_bfloat16 h0 = __float2bfloat16(xr[j].x), h1 = __float2bfloat16(xr[j].y);
        __nv_bfloat16 h2 = __float2bfloat16(xr[j].z), h3 = __float2bfloat16(xr[j].w);
        xh2[c2]     = __halves2bfloat162(h0, h1);
        xh2[c2 + 1] = __halves2bfloat162(h2, h3);
        xl2[c2]     = __halves2bfloat162(__float2bfloat16(xr[j].x - __bfloat162float(h0)),
                                         __float2bfloat16(xr[j].y - __bfloat162float(h1)));
        xl2[c2 + 1] = __halves2bfloat162(__float2bfloat16(xr[j].z - __bfloat162float(h2)),
                                         __float2bfloat16(xr[j].w - __bfloat162float(h3)));
    }

    int b = row >> 13, n = row & 8191;
#pragma unroll 1
    for (int h = 0; h < NHEAD; h++) {
        const float4* wp = (const float4*)(sw + h * 1024);
        float s = 0.f;
#pragma unroll
        for (int j = 0; j < 8; j++) {
            float4 w4 = wp[lane + 32 * j];
            s += xr[j].x * w4.x + xr[j].y * w4.y + xr[j].z * w4.z + xr[j].w * w4.w;
        }
#pragma unroll
        for (int off = 16; off; off >>= 1) s += __shfl_xor_sync(0xffffffffu, s, off);
        if (lane == 0) {
            float z = s + delta[h];
            lf[((size_t)(b * NHEAD + h)) * SEQ + n] =
                fminf(z, 0.f) - log1pf(expf(-fabsf(z)));
        }
    }
}

// ---------------------------------------------------------------------------
// Pass A (parallel over all chunks): cumsum gates, intra-chunk output, dS.
// ---------------------------------------------------------------------------
__global__ void scan_intra_kernel(const float* __restrict__ q, const float* __restrict__ k,
                                  const float* __restrict__ v, float* __restrict__ lf,
                                  float* __restrict__ o, float* __restrict__ dS)
{
    extern __shared__ float sh[];
    float* sq  = sh;
    float* sk  = sq  + 128 * 65;
    float* sv  = sk  + 128 * 65;
    float* sA  = sv  + 128 * 65;
    float* slf = sA  + 128 * 129;
    float* sE  = slf + 128;
    float* sEi = sE  + 128;

    int chunk = blockIdx.x, bh = blockIdx.y;
    int b = bh >> 4, h = bh & 15;
    int tid = threadIdx.x;
    size_t base = ((size_t)(b * SEQ + chunk * CHUNK)) * DDIM + h * HDIM;

    for (int idx = tid; idx < CHUNK * HDIM; idx += 256) {
        int r = idx >> 6, c = idx & 63;
        size_t g = base + (size_t)r * DDIM + c;
        sq[r * 65 + c] = q[g];
        sk[r * 65 + c] = k[g];
        sv[r * 65 + c] = v[g];
    }
    size_t lfbase = (size_t)bh * SEQ + (size_t)chunk * CHUNK;
    if (tid < 128) slf[tid] = lf[lfbase + tid];
    __syncthreads();

    for (int off = 1; off < 128; off <<= 1) {
        float add = 0.f;
        if (tid < 128 && tid >= off) add = slf[tid - off];
        __syncthreads();
        if (tid < 128) slf[tid] += add;
        __syncthreads();
    }
    if (tid < 128) {
        float l = slf[tid];
        lf[lfbase + tid] = l;
        sE[tid]  = expf(l);
        sEi[tid] = expf(-l);
    }
    __syncthreads();

    int tx = tid & 15, ty = tid >> 4;

    {   // A = (q k^T) * decay, masked
        int i0 = ty * 8, j0 = tx * 8;
        float acc[8][8];
#pragma unroll
        for (int i = 0; i < 8; i++)
#pragma unroll
            for (int j = 0; j < 8; j++) acc[i][j] = 0.f;
        for (int d = 0; d < HDIM; d++) {
            float qr[8], kr[8];
#pragma unroll
            for (int i = 0; i < 8; i++) qr[i] = sq[(i0 + i) * 65 + d];
#pragma unroll
            for (int j = 0; j < 8; j++) kr[j] = sk[(j0 + j) * 65 + d];
#pragma unroll
            for (int i = 0; i < 8; i++)
#pragma unroll
                for (int j = 0; j < 8; j++) acc[i][j] += qr[i] * kr[j];
        }
#pragma unroll
        for (int i = 0; i < 8; i++) {
            float ei = sE[i0 + i];
#pragma unroll
            for (int j = 0; j < 8; j++) {
                float val = (j0 + j <= i0 + i) ? acc[i][j] * ei * sEi[j0 + j] : 0.f;
                sA[(i0 + i) * 129 + (j0 + j)] = val;
            }
        }
    }
    __syncthreads();

    float eL = sE[127];
    for (int idx = tid; idx < CHUNK * HDIM; idx += 256) {
        int r = idx >> 6, c = idx & 63;
        sk[r * 65 + c] *= eL * sEi[r];
    }
    __syncthreads();

    {   // o_intra = A @ v
        int i0 = ty * 8, d0 = tx * 4;
        float acc[8][4];
#pragma unroll
        for (int i = 0; i < 8; i++)
#pragma unroll
            for (int d = 0; d < 4; d++) acc[i][d] = 0.f;
        for (int j = 0; j < CHUNK; j++) {
            float vr[4];
#pragma unroll
            for (int d = 0; d < 4; d++) vr[d] = sv[j * 65 + d0 + d];
#pragma unroll
            for (int i = 0; i < 8; i++) {
                float a = sA[(i0 + i) * 129 + j];
#pragma unroll
                for (int d = 0; d < 4; d++) acc[i][d] += a * vr[d];
            }
        }
#pragma unroll
        for (int i = 0; i < 8; i++)
#pragma unroll
            for (int d = 0; d < 4; d++)
                o[base + (size_t)(i0 + i) * DDIM + d0 + d] = acc[i][d];
    }

    {   // dS = kd^T @ v
        int d0 = ty * 4, e0 = tx * 4;
        float acc[4][4];
#pragma unroll
        for (int a = 0; a < 4; a++)
#pragma unroll
            for (int e = 0; e < 4; e++) acc[a][e] = 0.f;
        for (int j = 0; j < CHUNK; j++) {
            float kr[4], vr[4];
#pragma unroll
            for (int a = 0; a < 4; a++) kr[a] = sk[j * 65 + d0 + a];
#pragma unroll
            for (int e = 0; e < 4; e++) vr[e] = sv[j * 65 + e0 + e];
#pragma unroll
            for (int a = 0; a < 4; a++)
#pragma unroll
                for (int e = 0; e < 4; e++) acc[a][e] += kr[a] * vr[e];
        }
        size_t sb2 = ((size_t)bh * NCHUNK + chunk) * (HDIM * HDIM);
#pragma unroll
        for (int a = 0; a < 4; a++)
#pragma unroll
            for (int e = 0; e < 4; e++)
                dS[sb2 + (size_t)(d0 + a) * HDIM + e0 + e] = acc[a][e];
    }
}

// ---------------------------------------------------------------------------
// Pass B: sequential 64-step state scan; grid (NBH, 8), 512 elems per block.
// ---------------------------------------------------------------------------
__global__ void scan_state_kernel(const float* __restrict__ dS, const float* __restrict__ lf,
                                  float* __restrict__ Sin)
{
    int bh = blockIdx.x, tid = threadIdx.x;
    int seg = blockIdx.y * 512;
    float S[2] = {0.f, 0.f};
    for (int chunk = 0; chunk < NCHUNK; chunk++) {
        size_t base = ((size_t)bh * NCHUNK + chunk) * (HDIM * HDIM) + seg;
        float eL = expf(lf[(size_t)bh * SEQ + chunk * CHUNK + (CHUNK - 1)]);
#pragma unroll
        for (int j = 0; j < 2; j++) {
            int idx = tid + j * 256;
            Sin[base + idx] = S[j];
            S[j] = eL * S[j] + dS[base + idx];
        }
    }
}

// ---------------------------------------------------------------------------
// Pass C: o += exp(l_i) * (q @ S_in)
// ---------------------------------------------------------------------------
__global__ void scan_inter_kernel(const float* __restrict__ q, const float* __restrict__ lf,
                                  const float* __restrict__ Sin, float* __restrict__ o)
{
    extern __shared__ float sh[];
    float* sq  = sh;
    float* sS  = sq + 128 * 65;
    float* slf = sS + 64 * 65;
    int chunk = blockIdx.x, bh = blockIdx.y;
    int b = bh >> 4, h = bh & 15;
    int tid = threadIdx.x;
    size_t base = ((size_t)(b * SEQ + chunk * CHUNK)) * DDIM + h * HDIM;

    for (int idx = tid; idx < CHUNK * HDIM; idx += 256) {
        int r = idx >> 6, c = idx & 63;
        sq[r * 65 + c] = q[base + (size_t)r * DDIM + c];
    }
    size_t sb2 = ((size_t)bh * NCHUNK + chunk) * (HDIM * HDIM);
    for (int idx = tid; idx < HDIM * HDIM; idx += 256)
        sS[(idx >> 6) * 65 + (idx & 63)] = Sin[sb2 + idx];
    if (tid < 128) slf[tid] = lf[(size_t)bh * SEQ + chunk * CHUNK + tid];
    __syncthreads();

    int tx = tid & 15, ty = tid >> 4;
    int i0 = ty * 8, d0 = tx * 4;
    float acc[8][4];
#pragma unroll
    for (int i = 0; i < 8; i++)
#pragma unroll
        for (int d = 0; d < 4; d++) acc[i][d] = 0.f;
    for (int e = 0; e < HDIM; e++) {
        float sr[4];
#pragma unroll
        for (int d = 0; d < 4; d++) sr[d] = sS[e * 65 + d0 + d];
#pragma unroll
        for (int i = 0; i < 8; i++) {
            float qv = sq[(i0 + i) * 65 + e];
#pragma unroll
            for (int d = 0; d < 4; d++) acc[i][d] += qv * sr[d];
        }
    }
#pragma unroll
    for (int i = 0; i < 8; i++) {
        float ei = expf(slf[i0 + i]);
#pragma unroll
        for (int d = 0; d < 4; d++) {
            size_t g = base + (size_t)(i0 + i) * DDIM + d0 + d;
            o[g] += ei * acc[i][d];
        }
    }
}

// ---------------------------------------------------------------------------
// RMSNorm over last dim (1024); emits (hi, lo) bf16 directly for the Wo GEMM.
// ---------------------------------------------------------------------------
__global__ void rmsnorm_kernel(const float* __restrict__ o, const float* __restrict__ w,
                               __nv_bfloat16* __restrict__ ohi, __nv_bfloat16* __restrict__ olo)
{
    __shared__ float red[8];
    size_t base = (size_t)blockIdx.x * 1024;
    int tid = threadIdx.x;
    float vals[4];
    float ss = 0.f;
#pragma unroll
    for (int j = 0; j < 4; j++) {
        float t = o[base + tid + j * 256];
        vals[j] = t;
        ss += t * t;
    }
#pragma unroll
    for (int off = 16; off; off >>= 1) ss += __shfl_xor_sync(0xffffffffu, ss, off);
    if ((tid & 31) == 0) red[tid >> 5] = ss;
    __syncthreads();
    float tot = red[0] + red[1] + red[2] + red[3] + red[4] + red[5] + red[6] + red[7];
    float scale = rsqrtf(tot * (1.f / 1024.f) + 1e-6f);
#pragma unroll
    for (int j = 0; j < 4; j++) {
        int c = tid + j * 256;
        float t = vals[j] * scale * w[c];
        __nv_bfloat16 h = __float2bfloat16(t);
        ohi[base + c] = h;
        olo[base + c] = __float2bfloat16(t - __bfloat162float(h));
    }
}

// ---------------------------------------------------------------------------
extern "C" void kernel_launch(void* const* d_in, const int* in_sizes, int n_in,
                              void* d_out, int out_size)
{
    const float* x  = (const float*)d_in[0];
    const float* Wq = (const float*)d_in[1];
    const float* Wk = (const float*)d_in[2];
    const float* Wv = (const float*)d_in[3];
    const float* Wo = (const float*)d_in[4];
    const float* Wf = (const float*)d_in[5];
    const float* dl = (const float*)d_in[6];
    const float* nw = (const float*)d_in[7];
    float* out = (float*)d_out;

    float *q, *k, *v, *o, *lf, *dS, *Sin;
    cudaGetSymbolAddress((void**)&q,   g_q);
    cudaGetSymbolAddress((void**)&k,   g_k);
    cudaGetSymbolAddress((void**)&v,   g_v);
    cudaGetSymbolAddress((void**)&o,   g_o);
    cudaGetSymbolAddress((void**)&lf,  g_lf);
    cudaGetSymbolAddress((void**)&dS,  g_dS);
    cudaGetSymbolAddress((void**)&Sin, g_Sin);

    __nv_bfloat16 *xhi, *xlo, *ohi, *olo;
    __nv_bfloat16 *wqh, *wql, *wkh, *wkl, *wvh, *wvl, *woh, *wol;
    cudaGetSymbolAddress((void**)&xhi, g_xhi);
    cudaGetSymbolAddress((void**)&xlo, g_xlo);
    cudaGetSymbolAddress((void**)&ohi, g_ohi);
    cudaGetSymbolAddress((void**)&olo, g_olo);
    cudaGetSymbolAddress((void**)&wqh, g_wqhi);
    cudaGetSymbolAddress((void**)&wql, g_wqlo);
    cudaGetSymbolAddress((void**)&wkh, g_wkhi);
    cudaGetSymbolAddress((void**)&wkl, g_wklo);
    cudaGetSymbolAddress((void**)&wvh, g_wvhi);
    cudaGetSymbolAddress((void**)&wvl, g_wvlo);
    cudaGetSymbolAddress((void**)&woh, g_wohi);
    cudaGetSymbolAddress((void**)&wol, g_wolo);

    const int SMEM_GEMM  = 2 * BUFB;                                  // 81920 B
    const int SMEM_INTRA = (3 * 128 * 65 + 128 * 129 + 3 * 128) * 4;  // 167424 B
    const int SMEM_INTER = (128 * 65 + 64 * 65 + 128) * 4;            // 50432 B
    const int SMEM_FG    = 16 * 1024 * 4;                             // 65536 B
    cudaFuncSetAttribute(gemm_mma, cudaFuncAttributeMaxDynamicSharedMemorySize, SMEM_GEMM);
    cudaFuncSetAttribute(scan_intra_kernel, cudaFuncAttributeMaxDynamicSharedMemorySize, SMEM_INTRA);
    cudaFuncSetAttribute(scan_inter_kernel, cudaFuncAttributeMaxDynamicSharedMemorySize, SMEM_INTER);
    cudaFuncSetAttribute(fgate2_kernel, cudaFuncAttributeMaxDynamicSharedMemorySize, SMEM_FG);

    const int N4W = DDIM * DDIM / 4;

    // Weight splits (small) + fused x-split inside fgate2
    split_kernel<<<N4W / 256, 256>>>(Wq, wqh, wql, N4W);
    split_kernel<<<N4W / 256, 256>>>(Wk, wkh, wkl, N4W);
    split_kernel<<<N4W / 256, 256>>>(Wv, wvh, wvl, N4W);
    split_kernel<<<N4W / 256, 256>>>(Wo, woh, wol, N4W);
    fgate2_kernel<<<MROWS / 8, 256, SMEM_FG>>>(x, Wf, dl, lf, xhi, xlo);

    dim3 gg(DDIM / GTN, MROWS / GTM);   // (8, 256)
    gemm_mma<<<gg, 256, SMEM_GEMM>>>(xhi, xlo, wqh, wql, q, 1);
    gemm_mma<<<gg, 256, SMEM_GEMM>>>(xhi, xlo, wkh, wkl, k, 1);
    gemm_mma<<<gg, 256, SMEM_GEMM>>>(xhi, xlo, wvh, wvl, v, 0);

    scan_intra_kernel<<<dim3(NCHUNK, NBH), 256, SMEM_INTRA>>>(q, k, v, lf, o, dS);
    scan_state_kernel<<<dim3(NBH, 8), 256>>>(dS, lf, Sin);
    scan_inter_kernel<<<dim3(NCHUNK, NBH), 256, SMEM_INTER>>>(q, lf, Sin, o);
    rmsnorm_kernel<<<MROWS, 256>>>(o, nw, ohi, olo);

    gemm_mma<<<gg, 256, SMEM_GEMM>>>(ohi, olo, woh, wol, out, 0);
}

// round 13
// speedup vs baseline: 2.2534x; 1.1450x over previous
#include <cuda_runtime.h>
#include <cuda_bf16.h>
#include <cstdint>

// Problem constants
#define MROWS  32768      // B*N
#define DDIM   1024
#define NHEAD  16
#define CHUNK  128
#define HDIM   64
#define NCHUNK 64         // N / CHUNK
#define SEQ    8192
#define NBH    64         // B*H

// GEMM tiling (mma.sync bf16, fused hi/lo)
#define GTM 128
#define GTN 128
#define GBK 32
#define PITCH 80          // smem row pitch in bytes (32 bf16 = 64B data + 16B pad)
#define NSTAGE 32         // 1024 / 32
#define TILEB (GTM * PITCH)          // 10240 B per tile
#define BUFB  (4 * TILEB)            // Ahi, Alo, Bhi, Blo per buffer

// Scan mma pitches
#define P1 144            // rows of 64 bf16 (128B data + 16B pad)
#define P2 272            // rows of 128 bf16 (256B data + 16B pad)

// scan_intra_mma smem offsets (bytes)
#define OFF_QHI  0
#define OFF_QLO  18432
#define OFF_A    0        // A_hi overlays q (written after q reads complete)
#define OFF_ALO  34816
#define OFF_KHI  69632
#define OFF_KLO  88064
#define OFF_VTHI 106496
#define OFF_VTLO 123904
#define OFF_KDHI 141312
#define OFF_KDLO 158720
#define OFF_LF   176128
#define OFF_SE   176640
#define OFF_SEI  177152
#define SMEM_INTRA_MMA 177664

// scan_inter_mma smem offsets
#define IOFF_QHI 0
#define IOFF_QLO 18432
#define IOFF_STH 36864
#define IOFF_STL 46080
#define IOFF_LF  55296
#define SMEM_INTER_MMA 55808

// ---------------------------------------------------------------------------
// Scratch (static __device__ allocations — no cudaMalloc anywhere)
// ---------------------------------------------------------------------------
__device__ float g_q[MROWS * DDIM];
__device__ float g_k[MROWS * DDIM];
__device__ float g_v[MROWS * DDIM];
__device__ float g_o[MROWS * DDIM];
__device__ float g_lf[NBH * SEQ];
__device__ float g_dS[NBH * NCHUNK * HDIM * HDIM];
__device__ float g_Sin[NBH * NCHUNK * HDIM * HDIM];

__device__ __nv_bfloat16 g_xhi[MROWS * DDIM];
__device__ __nv_bfloat16 g_xlo[MROWS * DDIM];
__device__ __nv_bfloat16 g_ohi[MROWS * DDIM];
__device__ __nv_bfloat16 g_olo[MROWS * DDIM];
__device__ __nv_bfloat16 g_wqhi[DDIM * DDIM];
__device__ __nv_bfloat16 g_wqlo[DDIM * DDIM];
__device__ __nv_bfloat16 g_wkhi[DDIM * DDIM];
__device__ __nv_bfloat16 g_wklo[DDIM * DDIM];
__device__ __nv_bfloat16 g_wvhi[DDIM * DDIM];
__device__ __nv_bfloat16 g_wvlo[DDIM * DDIM];
__device__ __nv_bfloat16 g_wohi[DDIM * DDIM];
__device__ __nv_bfloat16 g_wolo[DDIM * DDIM];

// ---------------------------------------------------------------------------
// PTX helpers (plain sm_80-era instructions only — nothing 'a'-gated)
// ---------------------------------------------------------------------------
static __device__ __forceinline__ uint32_t smem_u32(const void* p) {
    uint32_t a;
    asm("{ .reg .u64 t; cvta.to.shared.u64 t, %1; cvt.u32.u64 %0, t; }" : "=r"(a) : "l"(p));
    return a;
}
static __device__ __forceinline__ void cp16(uint32_t dst, const void* src) {
    asm volatile("cp.async.cg.shared.global [%0], [%1], 16;" :: "r"(dst), "l"(src));
}
static __device__ __forceinline__ void ldsm4(uint32_t* r, uint32_t addr) {
    asm volatile("ldmatrix.sync.aligned.m8n8.x4.shared.b16 {%0,%1,%2,%3}, [%4];"
                 : "=r"(r[0]), "=r"(r[1]), "=r"(r[2]), "=r"(r[3]) : "r"(addr));
}
static __device__ __forceinline__ void mma16816(float* d, const uint32_t* a,
                                                uint32_t b0, uint32_t b1) {
    asm volatile(
        "mma.sync.aligned.m16n8k16.row.col.f32.bf16.bf16.f32 "
        "{%0,%1,%2,%3}, {%4,%5,%6,%7}, {%8,%9}, {%0,%1,%2,%3};"
        : "+f"(d[0]), "+f"(d[1]), "+f"(d[2]), "+f"(d[3])
        : "r"(a[0]), "r"(a[1]), "r"(a[2]), "r"(a[3]), "r"(b0), "r"(b1));
}
// fp32 pair -> bf16x2 (hi) and bf16x2 (lo residual)
static __device__ __forceinline__ void split2(float a, float b, uint32_t& hi, uint32_t& lo) {
    __nv_bfloat16 ha = __float2bfloat16(a), hb = __float2bfloat16(b);
    __nv_bfloat162 h2 = __halves2bfloat162(ha, hb);
    __nv_bfloat162 l2 = __halves2bfloat162(__float2bfloat16(a - __bfloat162float(ha)),
                                           __float2bfloat16(b - __bfloat162float(hb)));
    hi = *(uint32_t*)&h2;
    lo = *(uint32_t*)&l2;
}

// ---------------------------------------------------------------------------
// Split fp32 -> (hi, lo) bf16 pair (used for the 4 weight matrices only).
// ---------------------------------------------------------------------------
__global__ void split_kernel(const float* __restrict__ src, __nv_bfloat16* __restrict__ hi,
                             __nv_bfloat16* __restrict__ lo, int n4)
{
    int i = blockIdx.x * blockDim.x + threadIdx.x;
    if (i >= n4) return;
    float4 v = ((const float4*)src)[i];
    uint32_t h0, l0, h1, l1;
    split2(v.x, v.y, h0, l0);
    split2(v.z, v.w, h1, l1);
    *(uint2*)((char*)hi + (size_t)i * 8) = make_uint2(h0, h1);
    *(uint2*)((char*)lo + (size_t)i * 8) = make_uint2(l0, l1);
}

// ---------------------------------------------------------------------------
// Fused-pass mma.sync bf16 split GEMM: C = act( (Ahi+Alo) . (Bhi+Blo)^T )
// ---------------------------------------------------------------------------
__global__ __launch_bounds__(256, 2) void gemm_mma(
    const __nv_bfloat16* __restrict__ Ahi, const __nv_bfloat16* __restrict__ Alo,
    const __nv_bfloat16* __restrict__ Bhi, const __nv_bfloat16* __restrict__ Blo,
    float* __restrict__ C, int act)
{
    extern __shared__ __align__(16) char smem[];   // 2 * BUFB = 81920 B
    const uint32_t sb = smem_u32(smem);

    const int tid = threadIdx.x, lane = tid & 31, wid = tid >> 5;
    const int wm = wid & 1, wn = wid >> 1;
    const int row0 = blockIdx.y * GTM, col0 = blockIdx.x * GTN;

    const int r0t = tid >> 2, c0t = (tid & 3) * 16;
    const int r1t = (tid + 256) >> 2;

#define PREFETCH(S, BUF)                                                            \
    do {                                                                            \
        int kk = (S) * GBK;                                                         \
        uint32_t bufb = sb + (uint32_t)(BUF) * BUFB;                                \
        const char* s0 = (const char*)Ahi + ((size_t)(row0) * DDIM + kk) * 2;       \
        const char* s1 = (const char*)Alo + ((size_t)(row0) * DDIM + kk) * 2;       \
        const char* s2 = (const char*)Bhi + ((size_t)(col0) * DDIM + kk) * 2;       \
        const char* s3 = (const char*)Blo + ((size_t)(col0) * DDIM + kk) * 2;       \
        cp16(bufb + 0 * TILEB + r0t * PITCH + c0t, s0 + (size_t)r0t * 2048 + c0t);  \
        cp16(bufb + 0 * TILEB + r1t * PITCH + c0t, s0 + (size_t)r1t * 2048 + c0t);  \
        cp16(bufb + 1 * TILEB + r0t * PITCH + c0t, s1 + (size_t)r0t * 2048 + c0t);  \
        cp16(bufb + 1 * TILEB + r1t * PITCH + c0t, s1 + (size_t)r1t * 2048 + c0t);  \
        cp16(bufb + 2 * TILEB + r0t * PITCH + c0t, s2 + (size_t)r0t * 2048 + c0t);  \
        cp16(bufb + 2 * TILEB + r1t * PITCH + c0t, s2 + (size_t)r1t * 2048 + c0t);  \
        cp16(bufb + 3 * TILEB + r0t * PITCH + c0t, s3 + (size_t)r0t * 2048 + c0t);  \
        cp16(bufb + 3 * TILEB + r1t * PITCH + c0t, s3 + (size_t)r1t * 2048 + c0t);  \
        asm volatile("cp.async.commit_group;" ::: "memory");                        \
    } while (0)

    float acc[4][4][4];
#pragma unroll
    for (int mf = 0; mf < 4; mf++)
#pragma unroll
        for (int nf = 0; nf < 4; nf++)
#pragma unroll
            for (int e = 0; e < 4; e++) acc[mf][nf][e] = 0.f;

    const int lrow = ((lane >> 3) & 1) * 8 + (lane & 7);
    const int lcol8 = (lane >> 4) * 8;

    PREFETCH(0, 0);
    PREFETCH(1, 1);

    for (int s = 0; s < NSTAGE; s++) {
        if (s < NSTAGE - 1) asm volatile("cp.async.wait_group 1;" ::: "memory");
        else                asm volatile("cp.async.wait_group 0;" ::: "memory");
        __syncthreads();

        const uint32_t bufb = sb + (uint32_t)(s & 1) * BUFB;
        const uint32_t aho = bufb + 0 * TILEB + (wm * 64) * PITCH;
        const uint32_t alo = bufb + 1 * TILEB + (wm * 64) * PITCH;
        const uint32_t bho = bufb + 2 * TILEB + (wn * 32) * PITCH;
        const uint32_t blo = bufb + 3 * TILEB + (wn * 32) * PITCH;
#pragma unroll
        for (int ks = 0; ks < GBK; ks += 16) {
            const uint32_t loff = (uint32_t)lrow * PITCH + (uint32_t)(ks + lcol8) * 2;
            uint32_t af[4][4];
            uint32_t bh[4][2], bl[4][2];
#pragma unroll
            for (int mf = 0; mf < 4; mf++)
                ldsm4(af[mf], aho + mf * 16 * PITCH + loff);
#pragma unroll
            for (int p = 0; p < 2; p++) {
                uint32_t t[4];
                ldsm4(t, bho + p * 16 * PITCH + loff);
                bh[2 * p + 0][0] = t[0]; bh[2 * p + 0][1] = t[2];
                bh[2 * p + 1][0] = t[1]; bh[2 * p + 1][1] = t[3];
            }
#pragma unroll
            for (int mf = 0; mf < 4; mf++)
#pragma unroll
                for (int nf = 0; nf < 4; nf++)
                    mma16816(acc[mf][nf], af[mf], bh[nf][0], bh[nf][1]);   // hi*hi
#pragma unroll
            for (int p = 0; p < 2; p++) {
                uint32_t t[4];
                ldsm4(t, blo + p * 16 * PITCH + loff);
                bl[2 * p + 0][0] = t[0]; bl[2 * p + 0][1] = t[2];
                bl[2 * p + 1][0] = t[1]; bl[2 * p + 1][1] = t[3];
            }
#pragma unroll
            for (int mf = 0; mf < 4; mf++)
#pragma unroll
                for (int nf = 0; nf < 4; nf++)
                    mma16816(acc[mf][nf], af[mf], bl[nf][0], bl[nf][1]);   // hi*lo
#pragma unroll
            for (int mf = 0; mf < 4; mf++)
                ldsm4(af[mf], alo + mf * 16 * PITCH + loff);               // reuse af
#pragma unroll
            for (int mf = 0; mf < 4; mf++)
#pragma unroll
                for (int nf = 0; nf < 4; nf++)
                    mma16816(acc[mf][nf], af[mf], bh[nf][0], bh[nf][1]);   // lo*hi
        }
        __syncthreads();
        if (s + 2 < NSTAGE) PREFETCH(s + 2, s & 1);
    }
#undef PREFETCH

    const int erow = row0 + wm * 64 + (lane >> 2);
    const int ecol = col0 + wn * 32 + (lane & 3) * 2;
#pragma unroll
    for (int mf = 0; mf < 4; mf++) {
#pragma unroll
        for (int nf = 0; nf < 4; nf++) {
            float t0 = acc[mf][nf][0], t1 = acc[mf][nf][1];
            float t2 = acc[mf][nf][2], t3 = acc[mf][nf][3];
            if (act) {
                t0 = t0 / (1.f + expf(-t0));
                t1 = t1 / (1.f + expf(-t1));
                t2 = t2 / (1.f + expf(-t2));
                t3 = t3 / (1.f + expf(-t3));
            }
            size_t g0 = (size_t)(erow + mf * 16) * DDIM + ecol + nf * 8;
            size_t g1 = (size_t)(erow + mf * 16 + 8) * DDIM + ecol + nf * 8;
            *(float2*)(C + g0) = make_float2(t0, t1);
            *(float2*)(C + g1) = make_float2(t2, t3);
        }
    }
}

// ---------------------------------------------------------------------------
// fgate2 + x-split fusion
// ---------------------------------------------------------------------------
__global__ __launch_bounds__(256) void fgate2_kernel(
    const float* __restrict__ x, const float* __restrict__ Wf,
    const float* __restrict__ delta, float* __restrict__ lf,
    __nv_bfloat16* __restrict__ xhi, __nv_bfloat16* __restrict__ xlo)
{
    extern __shared__ float sw[];  // 16*1024 floats = 64KB
    int tid = threadIdx.x, lane = tid & 31, warp = tid >> 5;
    for (int i = tid; i < 4096; i += 256)
        ((float4*)sw)[i] = ((const float4*)Wf)[i];
    __syncthreads();

    int row = blockIdx.x * 8 + warp;
    const float4* xp = (const float4*)(x + (size_t)row * 1024);
    float4 xr[8];
#pragma unroll
    for (int j = 0; j < 8; j++) xr[j] = xp[lane + 32 * j];

    uint2* xh2 = (uint2*)(xhi + (size_t)row * 1024);
    uint2* xl2 = (uint2*)(xlo + (size_t)row * 1024);
#pragma unroll
    for (int j = 0; j < 8; j++) {
        uint32_t h0, l0, h1, l1;
        split2(xr[j].x, xr[j].y, h0, l0);
        split2(xr[j].z, xr[j].w, h1, l1);
        xh2[lane + 32 * j] = make_uint2(h0, h1);
        xl2[lane + 32 * j] = make_uint2(l0, l1);
    }

    int b = row >> 13, n = row & 8191;
#pragma unroll 1
    for (int h = 0; h < NHEAD; h++) {
        const float4* wp = (const float4*)(sw + h * 1024);
        float s = 0.f;
#pragma unroll
        for (int j = 0; j < 8; j++) {
            float4 w4 = wp[lane + 32 * j];
            s += xr[j].x * w4.x + xr[j].y * w4.y + xr[j].z * w4.z + xr[j].w * w4.w;
        }
#pragma unroll
        for (int off = 16; off; off >>= 1) s += __shfl_xor_sync(0xffffffffu, s, off);
        if (lane == 0) {
            float z = s + delta[h];
            lf[((size_t)(b * NHEAD + h)) * SEQ + n] =
                fminf(z, 0.f) - log1pf(expf(-fabsf(z)));
        }
    }
}

// ---------------------------------------------------------------------------
// Pass A tensorized: per (chunk, bh)
//   products qk^T (decay+mask), A@v, kd^T@v all via hi/lo mma.sync bf16.
// ---------------------------------------------------------------------------
__global__ __launch_bounds__(256) void scan_intra_mma(
    const float* __restrict__ q, const float* __restrict__ k,
    const float* __restrict__ v, float* __restrict__ lf,
    float* __restrict__ o, float* __restrict__ dS)
{
    extern __shared__ __align__(16) char sm[];
    const uint32_t sb = smem_u32(sm);
    float* slf = (float*)(sm + OFF_LF);
    float* sE  = (float*)(sm + OFF_SE);
    float* sEi = (float*)(sm + OFF_SEI);

    const int chunk = blockIdx.x, bh = blockIdx.y;
    const int b = bh >> 4, h = bh & 15;
    const int tid = threadIdx.x, lane = tid & 31, wid = tid >> 5;
    const size_t base = ((size_t)(b * SEQ + chunk * CHUNK)) * DDIM + h * HDIM;

    // ---- load q, k hi/lo (d-contig, pitch P1) ----
#pragma unroll
    for (int i = 0; i < 8; i++) {
        int idx = tid + i * 256;
        int r = idx >> 4, c4 = idx & 15;
        size_t g = base + (size_t)r * DDIM + c4 * 4;
        float4 vq = *(const float4*)(q + g);
        float4 vk = *(const float4*)(k + g);
        uint32_t h0, l0, h1, l1;
        split2(vq.x, vq.y, h0, l0); split2(vq.z, vq.w, h1, l1);
        *(uint2*)(sm + OFF_QHI + r * P1 + c4 * 8) = make_uint2(h0, h1);
        *(uint2*)(sm + OFF_QLO + r * P1 + c4 * 8) = make_uint2(l0, l1);
        split2(vk.x, vk.y, h0, l0); split2(vk.z, vk.w, h1, l1);
        *(uint2*)(sm + OFF_KHI + r * P1 + c4 * 8) = make_uint2(h0, h1);
        *(uint2*)(sm + OFF_KLO + r * P1 + c4 * 8) = make_uint2(l0, l1);
    }
    // ---- v transposed (j-contig rows d, pitch P2) ----
#pragma unroll
    for (int i = 0; i < 32; i++) {
        int idx = tid + i * 256;
        int j = idx >> 6, d = idx & 63;
        float vv = v[base + (size_t)j * DDIM + d];
        __nv_bfloat16 hh = __float2bfloat16(vv);
        *(__nv_bfloat16*)(sm + OFF_VTHI + d * P2 + j * 2) = hh;
        *(__nv_bfloat16*)(sm + OFF_VTLO + d * P2 + j * 2) =
            __float2bfloat16(vv - __bfloat162float(hh));
    }
    size_t lfbase = (size_t)bh * SEQ + (size_t)chunk * CHUNK;
    if (tid < 128) slf[tid] = lf[lfbase + tid];
    __syncthreads();

    // inclusive cumsum of slf
    for (int off = 1; off < 128; off <<= 1) {
        float add = 0.f;
        if (tid < 128 && tid >= off) add = slf[tid - off];
        __syncthreads();
        if (tid < 128) slf[tid] += add;
        __syncthreads();
    }
    if (tid < 128) {
        float l = slf[tid];
        lf[lfbase + tid] = l;
        sE[tid]  = expf(l);
        sEi[tid] = expf(-l);
    }
    __syncthreads();

    // ---- build kd^T (j-contig rows d) from k smem: exact fp32 reconstruct ----
    const float eL = sE[127];
#pragma unroll
    for (int i = 0; i < 32; i++) {
        int idx = tid + i * 256;
        int j = idx >> 6, d = idx & 63;
        float kh = __bfloat162float(*(__nv_bfloat16*)(sm + OFF_KHI + j * P1 + d * 2));
        float kl = __bfloat162float(*(__nv_bfloat16*)(sm + OFF_KLO + j * P1 + d * 2));
        float val = (kh + kl) * (eL * sEi[j]);
        __nv_bfloat16 hh = __float2bfloat16(val);
        *(__nv_bfloat16*)(sm + OFF_KDHI + d * P2 + j * 2) = hh;
        *(__nv_bfloat16*)(sm + OFF_KDLO + d * P2 + j * 2) =
            __float2bfloat16(val - __bfloat162float(hh));
    }

    const int lrow = ((lane >> 3) & 1) * 8 + (lane & 7);
    const int lcol8 = (lane >> 4) * 8;
    const int r0 = lane >> 2, c0 = (lane & 3) * 2;

    // ---- product 1: A = q k^T (128x128x64), then decay+mask+split -> smem ----
    {
        const int wm = wid & 1, wn = wid >> 1;
        float acc[4][4][4];
#pragma unroll
        for (int a0 = 0; a0 < 4; a0++)
#pragma unroll
            for (int a1 = 0; a1 < 4; a1++)
#pragma unroll
                for (int a2 = 0; a2 < 4; a2++) acc[a0][a1][a2] = 0.f;

        const uint32_t aqh = sb + OFF_QHI + (wm * 64) * P1;
        const uint32_t aql = sb + OFF_QLO + (wm * 64) * P1;
        const uint32_t bkh = sb + OFF_KHI + (wn * 32) * P1;
        const uint32_t bkl = sb + OFF_KLO + (wn * 32) * P1;
#pragma unroll
        for (int ks = 0; ks < 64; ks += 16) {
            const uint32_t loff = (uint32_t)lrow * P1 + (uint32_t)(ks + lcol8) * 2;
            uint32_t af[4][4], bhf[4][2], blf[4][2];
#pragma unroll
            for (int mf = 0; mf < 4; mf++) ldsm4(af[mf], aqh + mf * 16 * P1 + loff);
#pragma unroll
            for (int p = 0; p < 2; p++) {
                uint32_t t[4];
                ldsm4(t, bkh + p * 16 * P1 + loff);
                bhf[2 * p + 0][0] = t[0]; bhf[2 * p + 0][1] = t[2];
                bhf[2 * p + 1][0] = t[1]; bhf[2 * p + 1][1] = t[3];
            }
#pragma unroll
            for (int mf = 0; mf < 4; mf++)
#pragma unroll
                for (int nf = 0; nf < 4; nf++)
                    mma16816(acc[mf][nf], af[mf], bhf[nf][0], bhf[nf][1]);
#pragma unroll
            for (int p = 0; p < 2; p++) {
                uint32_t t[4];
                ldsm4(t, bkl + p * 16 * P1 + loff);
                blf[2 * p + 0][0] = t[0]; blf[2 * p + 0][1] = t[2];
                blf[2 * p + 1][0] = t[1]; blf[2 * p + 1][1] = t[3];
            }
#pragma unroll
            for (int mf = 0; mf < 4; mf++)
#pragma unroll
                for (int nf = 0; nf < 4; nf++)
                    mma16816(acc[mf][nf], af[mf], blf[nf][0], blf[nf][1]);
#pragma unroll
            for (int mf = 0; mf < 4; mf++) ldsm4(af[mf], aql + mf * 16 * P1 + loff);
#pragma unroll
            for (int mf = 0; mf < 4; mf++)
#pragma unroll
                for (int nf = 0; nf < 4; nf++)
                    mma16816(acc[mf][nf], af[mf], bhf[nf][0], bhf[nf][1]);
        }
        __syncthreads();   // all q/k reads done; kdT build done

        // decay + causal mask + hi/lo split -> A smem (overlays q)
#pragma unroll
        for (int mf = 0; mf < 4; mf++) {
            int i1 = wm * 64 + mf * 16 + r0;
            int i2 = i1 + 8;
            float e1 = sE[i1], e2 = sE[i2];
#pragma unroll
            for (int nf = 0; nf < 4; nf++) {
                int j0 = wn * 32 + nf * 8 + c0;
                float ej0 = sEi[j0], ej1 = sEi[j0 + 1];
                float v00 = (j0     <= i1) ? acc[mf][nf][0] * e1 * ej0 : 0.f;
                float v01 = (j0 + 1 <= i1) ? acc[mf][nf][1] * e1 * ej1 : 0.f;
                float v10 = (j0     <= i2) ? acc[mf][nf][2] * e2 * ej0 : 0.f;
                float v11 = (j0 + 1 <= i2) ? acc[mf][nf][3] * e2 * ej1 : 0.f;
                uint32_t hi0, lo0, hi1, lo1;
                split2(v00, v01, hi0, lo0);
                split2(v10, v11, hi1, lo1);
                *(uint32_t*)(sm + OFF_A   + i1 * P2 + j0 * 2) = hi0;
                *(uint32_t*)(sm + OFF_ALO + i1 * P2 + j0 * 2) = lo0;
                *(uint32_t*)(sm + OFF_A   + i2 * P2 + j0 * 2) = hi1;
                *(uint32_t*)(sm + OFF_ALO + i2 * P2 + j0 * 2) = lo1;
            }
        }
    }
    __syncthreads();

    // ---- product 2: o_intra = A @ v  (128x64x128) ----
    {
        const int wm = wid & 1, wn = wid >> 1;   // wn: 16 d-cols each
        float acc[4][2][4];
#pragma unroll
        for (int a0 = 0; a0 < 4; a0++)
#pragma unroll
            for (int a1 = 0; a1 < 2; a1++)
#pragma unroll
                for (int a2 = 0; a2 < 4; a2++) acc[a0][a1][a2] = 0.f;

        const uint32_t aAh = sb + OFF_A    + (wm * 64) * P2;
        const uint32_t aAl = sb + OFF_ALO  + (wm * 64) * P2;
        const uint32_t bVh = sb + OFF_VTHI + (wn * 16) * P2;
        const uint32_t bVl = sb + OFF_VTLO + (wn * 16) * P2;
#pragma unroll
        for (int ks = 0; ks < 128; ks += 16) {
            const uint32_t loff = (uint32_t)lrow * P2 + (uint32_t)(ks + lcol8) * 2;
            uint32_t af[4][4], bhf[2][2], blf[2][2];
#pragma unroll
            for (int mf = 0; mf < 4; mf++) ldsm4(af[mf], aAh + mf * 16 * P2 + loff);
            {
                uint32_t t[4];
                ldsm4(t, bVh + loff);
                bhf[0][0] = t[0]; bhf[0][1] = t[2];
                bhf[1][0] = t[1]; bhf[1][1] = t[3];
            }
#pragma unroll
            for (int mf = 0; mf < 4; mf++)
#pragma unroll
                for (int nf = 0; nf < 2; nf++)
                    mma16816(acc[mf][nf], af[mf], bhf[nf][0], bhf[nf][1]);
            {
                uint32_t t[4];
                ldsm4(t, bVl + loff);
                blf[0][0] = t[0]; blf[0][1] = t[2];
                blf[1][0] = t[1]; blf[1][1] = t[3];
            }
#pragma unroll
            for (int mf = 0; mf < 4; mf++)
#pragma unroll
                for (int nf = 0; nf < 2; nf++)
                    mma16816(acc[mf][nf], af[mf], blf[nf][0], blf[nf][1]);
#pragma unroll
            for (int mf = 0; mf < 4; mf++) ldsm4(af[mf], aAl + mf * 16 * P2 + loff);
#pragma unroll
            for (int mf = 0; mf < 4; mf++)
#pragma unroll
                for (int nf = 0; nf < 2; nf++)
                    mma16816(acc[mf][nf], af[mf], bhf[nf][0], bhf[nf][1]);
        }
#pragma unroll
        for (int mf = 0; mf < 4; mf++) {
            int i1 = wm * 64 + mf * 16 + r0;
#pragma unroll
            for (int nf = 0; nf < 2; nf++) {
                int d0 = wn * 16 + nf * 8 + c0;
                *(float2*)(o + base + (size_t)i1 * DDIM + d0) =
                    make_float2(acc[mf][nf][0], acc[mf][nf][1]);
                *(float2*)(o + base + (size_t)(i1 + 8) * DDIM + d0) =
                    make_float2(acc[mf][nf][2], acc[mf][nf][3]);
            }
        }
    }

    // ---- product 3: dS = kd^T @ v  (64x64x128) ----
    {
        const int wm3 = wid & 3, wn3 = wid >> 2;  // 16 d-rows, 32 e-cols per warp
        float acc[4][4];
#pragma unroll
        for (int a0 = 0; a0 < 4; a0++)
#pragma unroll
            for (int a2 = 0; a2 < 4; a2++) acc[a0][a2] = 0.f;

        const uint32_t aKh = sb + OFF_KDHI + (wm3 * 16) * P2;
        const uint32_t aKl = sb + OFF_KDLO + (wm3 * 16) * P2;
        const uint32_t bVh = sb + OFF_VTHI + (wn3 * 32) * P2;
        const uint32_t bVl = sb + OFF_VTLO + (wn3 * 32) * P2;
#pragma unroll
        for (int ks = 0; ks < 128; ks += 16) {
            const uint32_t loff = (uint32_t)lrow * P2 + (uint32_t)(ks + lcol8) * 2;
            uint32_t af[4], afl[4], bhf[4][2], blf[4][2];
            ldsm4(af, aKh + loff);
#pragma unroll
            for (int p = 0; p < 2; p++) {
                uint32_t t[4];
                ldsm4(t, bVh + p * 16 * P2 + loff);
                bhf[2 * p + 0][0] = t[0]; bhf[2 * p + 0][1] = t[2];
                bhf[2 * p + 1][0] = t[1]; bhf[2 * p + 1][1] = t[3];
            }
#pragma unroll
            for (int nf = 0; nf < 4; nf++)
                mma16816(acc[nf], af, bhf[nf][0], bhf[nf][1]);
#pragma unroll
            for (int p = 0; p < 2; p++) {
                uint32_t t[4];
                ldsm4(t, bVl + p * 16 * P2 + loff);
                blf[2 * p + 0][0] = t[0]; blf[2 * p + 0][1] = t[2];
                blf[2 * p + 1][0] = t[1]; blf[2 * p + 1][1] = t[3];
            }
#pragma unroll
            for (int nf = 0; nf < 4; nf++)
                mma16816(acc[nf], af, blf[nf][0], blf[nf][1]);
            ldsm4(afl, aKl + loff);
#pragma unroll
            for (int nf = 0; nf < 4; nf++)
                mma16816(acc[nf], afl, bhf[nf][0], bhf[nf][1]);
        }
        size_t sb2 = ((size_t)bh * NCHUNK + chunk) * (HDIM * HDIM);
        int d1 = wm3 * 16 + r0;
#pragma unroll
        for (int nf = 0; nf < 4; nf++) {
            int e0 = wn3 * 32 + nf * 8 + c0;
            *(float2*)(dS + sb2 + (size_t)d1 * HDIM + e0) = make_float2(acc[nf][0], acc[nf][1]);
            *(float2*)(dS + sb2 + (size_t)(d1 + 8) * HDIM + e0) = make_float2(acc[nf][2], acc[nf][3]);
        }
    }
}

// ---------------------------------------------------------------------------
// Pass B: sequential 64-step state scan; grid (NBH, 8), 512 elems per block.
// ---------------------------------------------------------------------------
__global__ void scan_state_kernel(const float* __restrict__ dS, const float* __restrict__ lf,
                                  float* __restrict__ Sin)
{
    int bh = blockIdx.x, tid = threadIdx.x;
    int seg = blockIdx.y * 512;
    float S[2] = {0.f, 0.f};
    for (int chunk = 0; chunk < NCHUNK; chunk++) {
        size_t base = ((size_t)bh * NCHUNK + chunk) * (HDIM * HDIM) + seg;
        float eL = expf(lf[(size_t)bh * SEQ + chunk * CHUNK + (CHUNK - 1)]);
#pragma unroll
        for (int j = 0; j < 2; j++) {
            int idx = tid + j * 256;
            Sin[base + idx] = S[j];
            S[j] = eL * S[j] + dS[base + idx];
        }
    }
}

// ---------------------------------------------------------------------------
// Pass C tensorized: o += exp(l_i) * (q @ S_in)
// ---------------------------------------------------------------------------
__global__ __launch_bounds__(256) void scan_inter_mma(
    const float* __restrict__ q, const float* __restrict__ lf,
    const float* __restrict__ Sin, float* __restrict__ o)
{
    extern __shared__ __align__(16) char sm[];
    const uint32_t sb = smem_u32(sm);
    float* slf = (float*)(sm + IOFF_LF);

    const int chunk = blockIdx.x, bh = blockIdx.y;
    const int b = bh >> 4, h = bh & 15;
    const int tid = threadIdx.x, lane = tid & 31, wid = tid >> 5;
    const size_t base = ((size_t)(b * SEQ + chunk * CHUNK)) * DDIM + h * HDIM;

    // load q hi/lo (d-contig, pitch P1)
#pragma unroll
    for (int i = 0; i < 8; i++) {
        int idx = tid + i * 256;
        int r = idx >> 4, c4 = idx & 15;
        float4 vq = *(const float4*)(q + base + (size_t)r * DDIM + c4 * 4);
        uint32_t h0, l0, h1, l1;
        split2(vq.x, vq.y, h0, l0); split2(vq.z, vq.w, h1, l1);
        *(uint2*)(sm + IOFF_QHI + r * P1 + c4 * 8) = make_uint2(h0, h1);
        *(uint2*)(sm + IOFF_QLO + r * P1 + c4 * 8) = make_uint2(l0, l1);
    }
    // load Sin transposed: Bs[e][d] = S[d][e]  (pitch P1, rows e)
    size_t sb2 = ((size_t)bh * NCHUNK + chunk) * (HDIM * HDIM);
#pragma unroll
    for (int i = 0; i < 16; i++) {
        int idx = tid + i * 256;
        int d = idx >> 6, e = idx & 63;
        float sv = Sin[sb2 + (size_t)d * HDIM + e];
        __nv_bfloat16 hh = __float2bfloat16(sv);
        *(__nv_bfloat16*)(sm + IOFF_STH + e * P1 + d * 2) = hh;
        *(__nv_bfloat16*)(sm + IOFF_STL + e * P1 + d * 2) =
            __float2bfloat16(sv - __bfloat162float(hh));
    }
    if (tid < 128) slf[tid] = lf[(size_t)bh * SEQ + chunk * CHUNK + tid];
    __syncthreads();

    const int lrow = ((lane >> 3) & 1) * 8 + (lane & 7);
    const int lcol8 = (lane >> 4) * 8;
    const int r0 = lane >> 2, c0 = (lane & 3) * 2;
    const int wm = wid & 1, wn = wid >> 1;   // 64 rows, 16 e-cols per warp

    float acc[4][2][4];
#pragma unroll
    for (int a0 = 0; a0 < 4; a0++)
#pragma unroll
        for (int a1 = 0; a1 < 2; a1++)
#pragma unroll
            for (int a2 = 0; a2 < 4; a2++) acc[a0][a1][a2] = 0.f;

    const uint32_t aQh = sb + IOFF_QHI + (wm * 64) * P1;
    const uint32_t aQl = sb + IOFF_QLO + (wm * 64) * P1;
    const uint32_t bSh = sb + IOFF_STH + (wn * 16) * P1;
    const uint32_t bSl = sb + IOFF_STL + (wn * 16) * P1;
#pragma unroll
    for (int ks = 0; ks < 64; ks += 16) {
        const uint32_t loff = (uint32_t)lrow * P1 + (uint32_t)(ks + lcol8) * 2;
        uint32_t af[4][4], bhf[2][2], blf[2][2];
#pragma unroll
        for (int mf = 0; mf < 4; mf++) ldsm4(af[mf], aQh + mf * 16 * P1 + loff);
        {
            uint32_t t[4];
            ldsm4(t, bSh + loff);
            bhf[0][0] = t[0]; bhf[0][1] = t[2];
            bhf[1][0] = t[1]; bhf[1][1] = t[3];
        }
#pragma unroll
        for (int mf = 0; mf < 4; mf++)
#pragma unroll
            for (int nf = 0; nf < 2; nf++)
                mma16816(acc[mf][nf], af[mf], bhf[nf][0], bhf[nf][1]);
        {
            uint32_t t[4];
            ldsm4(t, bSl + loff);
            blf[0][0] = t[0]; blf[0][1] = t[2];
            blf[1][0] = t[1]; blf[1][1] = t[3];
        }
#pragma unroll
        for (int mf = 0; mf < 4; mf++)
#pragma unroll
            for (int nf = 0; nf < 2; nf++)
                mma16816(acc[mf][nf], af[mf], blf[nf][0], blf[nf][1]);
#pragma unroll
        for (int mf = 0; mf < 4; mf++) ldsm4(af[mf], aQl + mf * 16 * P1 + loff);
#pragma unroll
        for (int mf = 0; mf < 4; mf++)
#pragma unroll
            for (int nf = 0; nf < 2; nf++)
                mma16816(acc[mf][nf], af[mf], bhf[nf][0], bhf[nf][1]);
    }

#pragma unroll
    for (int mf = 0; mf < 4; mf++) {
        int i1 = wm * 64 + mf * 16 + r0;
        float e1 = expf(slf[i1]), e2 = expf(slf[i1 + 8]);
#pragma unroll
        for (int nf = 0; nf < 2; nf++) {
            int d0 = wn * 16 + nf * 8 + c0;
            float2* p1 = (float2*)(o + base + (size_t)i1 * DDIM + d0);
            float2 c1 = *p1;
            c1.x += e1 * acc[mf][nf][0];
            c1.y += e1 * acc[mf][nf][1];
            *p1 = c1;
            float2* p2 = (float2*)(o + base + (size_t)(i1 + 8) * DDIM + d0);
            float2 c2 = *p2;
            c2.x += e2 * acc[mf][nf][2];
            c2.y += e2 * acc[mf][nf][3];
            *p2 = c2;
        }
    }
}

// ---------------------------------------------------------------------------
// RMSNorm over last dim (1024); emits (hi, lo) bf16 directly for the Wo GEMM.
// ---------------------------------------------------------------------------
__global__ void rmsnorm_kernel(const float* __restrict__ o, const float* __restrict__ w,
                               __nv_bfloat16* __restrict__ ohi, __nv_bfloat16* __restrict__ olo)
{
    __shared__ float red[8];
    size_t base = (size_t)blockIdx.x * 1024;
    int tid = threadIdx.x;
    float vals[4];
    float ss = 0.f;
#pragma unroll
    for (int j = 0; j < 4; j++) {
        float t = o[base + tid + j * 256];
        vals[j] = t;
        ss += t * t;
    }
#pragma unroll
    for (int off = 16; off; off >>= 1) ss += __shfl_xor_sync(0xffffffffu, ss, off);
    if ((tid & 31) == 0) red[tid >> 5] = ss;
    __syncthreads();
    float tot = red[0] + red[1] + red[2] + red[3] + red[4] + red[5] + red[6] + red[7];
    float scale = rsqrtf(tot * (1.f / 1024.f) + 1e-6f);
#pragma unroll
    for (int j = 0; j < 4; j++) {
        int c = tid + j * 256;
        float t = vals[j] * scale * w[c];
        __nv_bfloat16 h = __float2bfloat16(t);
        ohi[base + c] = h;
        olo[base + c] = __float2bfloat16(t - __bfloat162float(h));
    }
}

// ---------------------------------------------------------------------------
extern "C" void kernel_launch(void* const* d_in, const int* in_sizes, int n_in,
                              void* d_out, int out_size)
{
    const float* x  = (const float*)d_in[0];
    const float* Wq = (const float*)d_in[1];
    const float* Wk = (const float*)d_in[2];
    const float* Wv = (const float*)d_in[3];
    const float* Wo = (const float*)d_in[4];
    const float* Wf = (const float*)d_in[5];
    const float* dl = (const float*)d_in[6];
    const float* nw = (const float*)d_in[7];
    float* out = (float*)d_out;

    float *q, *k, *v, *o, *lf, *dS, *Sin;
    cudaGetSymbolAddress((void**)&q,   g_q);
    cudaGetSymbolAddress((void**)&k,   g_k);
    cudaGetSymbolAddress((void**)&v,   g_v);
    cudaGetSymbolAddress((void**)&o,   g_o);
    cudaGetSymbolAddress((void**)&lf,  g_lf);
    cudaGetSymbolAddress((void**)&dS,  g_dS);
    cudaGetSymbolAddress((void**)&Sin, g_Sin);

    __nv_bfloat16 *xhi, *xlo, *ohi, *olo;
    __nv_bfloat16 *wqh, *wql, *wkh, *wkl, *wvh, *wvl, *woh, *wol;
    cudaGetSymbolAddress((void**)&xhi, g_xhi);
    cudaGetSymbolAddress((void**)&xlo, g_xlo);
    cudaGetSymbolAddress((void**)&ohi, g_ohi);
    cudaGetSymbolAddress((void**)&olo, g_olo);
    cudaGetSymbolAddress((void**)&wqh, g_wqhi);
    cudaGetSymbolAddress((void**)&wql, g_wqlo);
    cudaGetSymbolAddress((void**)&wkh, g_wkhi);
    cudaGetSymbolAddress((void**)&wkl, g_wklo);
    cudaGetSymbolAddress((void**)&wvh, g_wvhi);
    cudaGetSymbolAddress((void**)&wvl, g_wvlo);
    cudaGetSymbolAddress((void**)&woh, g_wohi);
    cudaGetSymbolAddress((void**)&wol, g_wolo);

    const int SMEM_GEMM = 2 * BUFB;         // 81920 B
    const int SMEM_FG   = 16 * 1024 * 4;    // 65536 B
    cudaFuncSetAttribute(gemm_mma, cudaFuncAttributeMaxDynamicSharedMemorySize, SMEM_GEMM);
    cudaFuncSetAttribute(fgate2_kernel, cudaFuncAttributeMaxDynamicSharedMemorySize, SMEM_FG);
    cudaFuncSetAttribute(scan_intra_mma, cudaFuncAttributeMaxDynamicSharedMemorySize, SMEM_INTRA_MMA);
    cudaFuncSetAttribute(scan_inter_mma, cudaFuncAttributeMaxDynamicSharedMemorySize, SMEM_INTER_MMA);

    const int N4W = DDIM * DDIM / 4;

    split_kernel<<<N4W / 256, 256>>>(Wq, wqh, wql, N4W);
    split_kernel<<<N4W / 256, 256>>>(Wk, wkh, wkl, N4W);
    split_kernel<<<N4W / 256, 256>>>(Wv, wvh, wvl, N4W);
    split_kernel<<<N4W / 256, 256>>>(Wo, woh, wol, N4W);
    fgate2_kernel<<<MROWS / 8, 256, SMEM_FG>>>(x, Wf, dl, lf, xhi, xlo);

    dim3 gg(DDIM / GTN, MROWS / GTM);   // (8, 256)
    gemm_mma<<<gg, 256, SMEM_GEMM>>>(xhi, xlo, wqh, wql, q, 1);
    gemm_mma<<<gg, 256, SMEM_GEMM>>>(xhi, xlo, wkh, wkl, k, 1);
    gemm_mma<<<gg, 256, SMEM_GEMM>>>(xhi, xlo, wvh, wvl, v, 0);

    scan_intra_mma<<<dim3(NCHUNK, NBH), 256, SMEM_INTRA_MMA>>>(q, k, v, lf, o, dS);
    scan_state_kernel<<<dim3(NBH, 8), 256>>>(dS, lf, Sin);
    scan_inter_mma<<<dim3(NCHUNK, NBH), 256, SMEM_INTER_MMA>>>(q, lf, Sin, o);
    rmsnorm_kernel<<<MROWS, 256>>>(o, nw, ohi, olo);

    gemm_mma<<<gg, 256, SMEM_GEMM>>>(ohi, olo, woh, wol, out, 0);
}

// round 14
// speedup vs baseline: 2.4097x; 1.0694x over previous
#include <cuda_runtime.h>
#include <cuda_bf16.h>
#include <cstdint>

// Problem constants
#define MROWS  32768      // B*N
#define DDIM   1024
#define NHEAD  16
#define CHUNK  128
#define HDIM   64
#define NCHUNK 64         // N / CHUNK
#define SEQ    8192
#define NBH    64         // B*H

// GEMM tiling (mma.sync bf16, fused hi/lo)
#define GTM 128
#define GTN 128
#define GBK 32
#define PITCH 80
#define NSTAGE 32
#define TILEB (GTM * PITCH)
#define BUFB  (4 * TILEB)

// Scan mma pitches
#define P1 144            // rows of 64 bf16 (128B data + 16B pad)
#define P2 272            // rows of 128 bf16 (256B data + 16B pad)
#define PS 144            // v staging pitch

// scan_intra_mma smem offsets (bytes)
#define OFF_QHI  0
#define OFF_QLO  18432
#define OFF_KHI  36864
#define OFF_KLO  55296
#define OFF_VTHI 73728
#define OFF_VTLO 108544
#define OFF_KDHI 143360
#define OFF_KDLO 178176
#define OFF_VSH  143360   // v staging (hi) — overlays kd region, freed before kd build
#define OFF_VSL  161792   // v staging (lo)
#define OFF_A    0        // A_hi overlays q (written after q/k reads complete)
#define OFF_ALO  34816
#define OFF_SE   212992
#define OFF_SEI  213504
#define SMEM_INTRA_MMA 214016

// scan_inter_mma smem offsets
#define IOFF_QHI 0
#define IOFF_QLO 18432
#define IOFF_STH 36864
#define IOFF_STL 46080
#define IOFF_LF  55296
#define SMEM_INTER_MMA 55808

// ---------------------------------------------------------------------------
// Scratch (static __device__ allocations — no cudaMalloc anywhere)
// ---------------------------------------------------------------------------
__device__ float g_o[MROWS * DDIM];
__device__ float g_lf[NBH * SEQ];
__device__ float g_dS[NBH * NCHUNK * HDIM * HDIM];
__device__ float g_Sin[NBH * NCHUNK * HDIM * HDIM];

__device__ __nv_bfloat16 g_xhi[MROWS * DDIM];
__device__ __nv_bfloat16 g_xlo[MROWS * DDIM];
__device__ __nv_bfloat16 g_qhi[MROWS * DDIM];
__device__ __nv_bfloat16 g_qlo[MROWS * DDIM];
__device__ __nv_bfloat16 g_khi[MROWS * DDIM];
__device__ __nv_bfloat16 g_klo[MROWS * DDIM];
__device__ __nv_bfloat16 g_vhi[MROWS * DDIM];
__device__ __nv_bfloat16 g_vlo[MROWS * DDIM];
__device__ __nv_bfloat16 g_ohi[MROWS * DDIM];
__device__ __nv_bfloat16 g_olo[MROWS * DDIM];
__device__ __nv_bfloat16 g_wqhi[DDIM * DDIM];
__device__ __nv_bfloat16 g_wqlo[DDIM * DDIM];
__device__ __nv_bfloat16 g_wkhi[DDIM * DDIM];
__device__ __nv_bfloat16 g_wklo[DDIM * DDIM];
__device__ __nv_bfloat16 g_wvhi[DDIM * DDIM];
__device__ __nv_bfloat16 g_wvlo[DDIM * DDIM];
__device__ __nv_bfloat16 g_wohi[DDIM * DDIM];
__device__ __nv_bfloat16 g_wolo[DDIM * DDIM];

// ---------------------------------------------------------------------------
// PTX helpers (plain sm_80-era instructions only — nothing 'a'-gated)
// ---------------------------------------------------------------------------
static __device__ __forceinline__ uint32_t smem_u32(const void* p) {
    uint32_t a;
    asm("{ .reg .u64 t; cvta.to.shared.u64 t, %1; cvt.u32.u64 %0, t; }" : "=r"(a) : "l"(p));
    return a;
}
static __device__ __forceinline__ void cp16(uint32_t dst, const void* src) {
    asm volatile("cp.async.cg.shared.global [%0], [%1], 16;" :: "r"(dst), "l"(src));
}
static __device__ __forceinline__ void ldsm4(uint32_t* r, uint32_t addr) {
    asm volatile("ldmatrix.sync.aligned.m8n8.x4.shared.b16 {%0,%1,%2,%3}, [%4];"
                 : "=r"(r[0]), "=r"(r[1]), "=r"(r[2]), "=r"(r[3]) : "r"(addr));
}
static __device__ __forceinline__ void mma16816(float* d, const uint32_t* a,
                                                uint32_t b0, uint32_t b1) {
    asm volatile(
        "mma.sync.aligned.m16n8k16.row.col.f32.bf16.bf16.f32 "
        "{%0,%1,%2,%3}, {%4,%5,%6,%7}, {%8,%9}, {%0,%1,%2,%3};"
        : "+f"(d[0]), "+f"(d[1]), "+f"(d[2]), "+f"(d[3])
        : "r"(a[0]), "r"(a[1]), "r"(a[2]), "r"(a[3]), "r"(b0), "r"(b1));
}
// fp32 pair -> bf16x2 (hi) and bf16x2 (lo residual); a in low half.
static __device__ __forceinline__ void split2(float a, float b, uint32_t& hi, uint32_t& lo) {
    __nv_bfloat16 ha = __float2bfloat16(a), hb = __float2bfloat16(b);
    __nv_bfloat162 h2 = __halves2bfloat162(ha, hb);
    __nv_bfloat162 l2 = __halves2bfloat162(__float2bfloat16(a - __bfloat162float(ha)),
                                           __float2bfloat16(b - __bfloat162float(hb)));
    hi = *(uint32_t*)&h2;
    lo = *(uint32_t*)&l2;
}
// element t (0..3) of a uint2 viewed as 4 bf16
static __device__ __forceinline__ float bf_at(uint2 u, int t) {
    uint32_t w = (t < 2) ? u.x : u.y;
    uint16_t hb = (t & 1) ? (uint16_t)(w >> 16) : (uint16_t)(w & 0xffff);
    return __bfloat162float(__ushort_as_bfloat16(hb));
}

// ---------------------------------------------------------------------------
// Split fp32 -> (hi, lo) bf16 pair (weight matrices only).
// ---------------------------------------------------------------------------
__global__ void split_kernel(const float* __restrict__ src, __nv_bfloat16* __restrict__ hi,
                             __nv_bfloat16* __restrict__ lo, int n4)
{
    int i = blockIdx.x * blockDim.x + threadIdx.x;
    if (i >= n4) return;
    float4 v = ((const float4*)src)[i];
    uint32_t h0, l0, h1, l1;
    split2(v.x, v.y, h0, l0);
    split2(v.z, v.w, h1, l1);
    *(uint2*)((char*)hi + (size_t)i * 8) = make_uint2(h0, h1);
    *(uint2*)((char*)lo + (size_t)i * 8) = make_uint2(l0, l1);
}

// ---------------------------------------------------------------------------
// Per-chunk inclusive cumsum of lf (in place). grid 4096, block 128.
// ---------------------------------------------------------------------------
__global__ void cumsum_kernel(float* __restrict__ lf)
{
    __shared__ float s[128];
    size_t base = (size_t)blockIdx.x * 128;
    int tid = threadIdx.x;
    s[tid] = lf[base + tid];
    __syncthreads();
    for (int off = 1; off < 128; off <<= 1) {
        float add = (tid >= off) ? s[tid - off] : 0.f;
        __syncthreads();
        s[tid] += add;
        __syncthreads();
    }
    lf[base + tid] = s[tid];
}

// ---------------------------------------------------------------------------
// Fused-pass mma.sync bf16 split GEMM: C = act( (Ahi+Alo).(Bhi+Blo)^T )
// split=1: write bf16 hi/lo to Chi/Clo;  split=0: write fp32 to C.
// ---------------------------------------------------------------------------
__global__ __launch_bounds__(256, 2) void gemm_mma(
    const __nv_bfloat16* __restrict__ Ahi, const __nv_bfloat16* __restrict__ Alo,
    const __nv_bfloat16* __restrict__ Bhi, const __nv_bfloat16* __restrict__ Blo,
    float* __restrict__ C, __nv_bfloat16* __restrict__ Chi, __nv_bfloat16* __restrict__ Clo,
    int act, int split)
{
    extern __shared__ __align__(16) char smem[];   // 2 * BUFB = 81920 B
    const uint32_t sb = smem_u32(smem);

    const int tid = threadIdx.x, lane = tid & 31, wid = tid >> 5;
    const int wm = wid & 1, wn = wid >> 1;
    const int row0 = blockIdx.y * GTM, col0 = blockIdx.x * GTN;

    const int r0t = tid >> 2, c0t = (tid & 3) * 16;
    const int r1t = (tid + 256) >> 2;

#define PREFETCH(S, BUF)                                                            \
    do {                                                                            \
        int kk = (S) * GBK;                                                         \
        uint32_t bufb = sb + (uint32_t)(BUF) * BUFB;                                \
        const char* s0 = (const char*)Ahi + ((size_t)(row0) * DDIM + kk) * 2;       \
        const char* s1 = (const char*)Alo + ((size_t)(row0) * DDIM + kk) * 2;       \
        const char* s2 = (const char*)Bhi + ((size_t)(col0) * DDIM + kk) * 2;       \
        const char* s3 = (const char*)Blo + ((size_t)(col0) * DDIM + kk) * 2;       \
        cp16(bufb + 0 * TILEB + r0t * PITCH + c0t, s0 + (size_t)r0t * 2048 + c0t);  \
        cp16(bufb + 0 * TILEB + r1t * PITCH + c0t, s0 + (size_t)r1t * 2048 + c0t);  \
        cp16(bufb + 1 * TILEB + r0t * PITCH + c0t, s1 + (size_t)r0t * 2048 + c0t);  \
        cp16(bufb + 1 * TILEB + r1t * PITCH + c0t, s1 + (size_t)r1t * 2048 + c0t);  \
        cp16(bufb + 2 * TILEB + r0t * PITCH + c0t, s2 + (size_t)r0t * 2048 + c0t);  \
        cp16(bufb + 2 * TILEB + r1t * PITCH + c0t, s2 + (size_t)r1t * 2048 + c0t);  \
        cp16(bufb + 3 * TILEB + r0t * PITCH + c0t, s3 + (size_t)r0t * 2048 + c0t);  \
        cp16(bufb + 3 * TILEB + r1t * PITCH + c0t, s3 + (size_t)r1t * 2048 + c0t);  \
        asm volatile("cp.async.commit_group;" ::: "memory");                        \
    } while (0)

    float acc[4][4][4];
#pragma unroll
    for (int mf = 0; mf < 4; mf++)
#pragma unroll
        for (int nf = 0; nf < 4; nf++)
#pragma unroll
            for (int e = 0; e < 4; e++) acc[mf][nf][e] = 0.f;

    const int lrow = ((lane >> 3) & 1) * 8 + (lane & 7);
    const int lcol8 = (lane >> 4) * 8;

    PREFETCH(0, 0);
    PREFETCH(1, 1);

    for (int s = 0; s < NSTAGE; s++) {
        if (s < NSTAGE - 1) asm volatile("cp.async.wait_group 1;" ::: "memory");
        else                asm volatile("cp.async.wait_group 0;" ::: "memory");
        __syncthreads();

        const uint32_t bufb = sb + (uint32_t)(s & 1) * BUFB;
        const uint32_t aho = bufb + 0 * TILEB + (wm * 64) * PITCH;
        const uint32_t alo = bufb + 1 * TILEB + (wm * 64) * PITCH;
        const uint32_t bho = bufb + 2 * TILEB + (wn * 32) * PITCH;
        const uint32_t blo = bufb + 3 * TILEB + (wn * 32) * PITCH;
#pragma unroll
        for (int ks = 0; ks < GBK; ks += 16) {
            const uint32_t loff = (uint32_t)lrow * PITCH + (uint32_t)(ks + lcol8) * 2;
            uint32_t af[4][4];
            uint32_t bh[4][2], bl[4][2];
#pragma unroll
            for (int mf = 0; mf < 4; mf++)
                ldsm4(af[mf], aho + mf * 16 * PITCH + loff);
#pragma unroll
            for (int p = 0; p < 2; p++) {
                uint32_t t[4];
                ldsm4(t, bho + p * 16 * PITCH + loff);
                bh[2 * p + 0][0] = t[0]; bh[2 * p + 0][1] = t[2];
                bh[2 * p + 1][0] = t[1]; bh[2 * p + 1][1] = t[3];
            }
#pragma unroll
            for (int mf = 0; mf < 4; mf++)
#pragma unroll
                for (int nf = 0; nf < 4; nf++)
                    mma16816(acc[mf][nf], af[mf], bh[nf][0], bh[nf][1]);   // hi*hi
#pragma unroll
            for (int p = 0; p < 2; p++) {
                uint32_t t[4];
                ldsm4(t, blo + p * 16 * PITCH + loff);
                bl[2 * p + 0][0] = t[0]; bl[2 * p + 0][1] = t[2];
                bl[2 * p + 1][0] = t[1]; bl[2 * p + 1][1] = t[3];
            }
#pragma unroll
            for (int mf = 0; mf < 4; mf++)
#pragma unroll
                for (int nf = 0; nf < 4; nf++)
                    mma16816(acc[mf][nf], af[mf], bl[nf][0], bl[nf][1]);   // hi*lo
#pragma unroll
            for (int mf = 0; mf < 4; mf++)
                ldsm4(af[mf], alo + mf * 16 * PITCH + loff);               // reuse af
#pragma unroll
            for (int mf = 0; mf < 4; mf++)
#pragma unroll
                for (int nf = 0; nf < 4; nf++)
                    mma16816(acc[mf][nf], af[mf], bh[nf][0], bh[nf][1]);   // lo*hi
        }
        __syncthreads();
        if (s + 2 < NSTAGE) PREFETCH(s + 2, s & 1);
    }
#undef PREFETCH

    const int erow = row0 + wm * 64 + (lane >> 2);
    const int ecol = col0 + wn * 32 + (lane & 3) * 2;
#pragma unroll
    for (int mf = 0; mf < 4; mf++) {
#pragma unroll
        for (int nf = 0; nf < 4; nf++) {
            float t0 = acc[mf][nf][0], t1 = acc[mf][nf][1];
            float t2 = acc[mf][nf][2], t3 = acc[mf][nf][3];
            if (act) {
                t0 = t0 / (1.f + expf(-t0));
                t1 = t1 / (1.f + expf(-t1));
                t2 = t2 / (1.f + expf(-t2));
                t3 = t3 / (1.f + expf(-t3));
            }
            size_t g0 = (size_t)(erow + mf * 16) * DDIM + ecol + nf * 8;
            size_t g1 = (size_t)(erow + mf * 16 + 8) * DDIM + ecol + nf * 8;
            if (!split) {
                *(float2*)(C + g0) = make_float2(t0, t1);
                *(float2*)(C + g1) = make_float2(t2, t3);
            } else {
                uint32_t h0, l0, h1, l1;
                split2(t0, t1, h0, l0);
                split2(t2, t3, h1, l1);
                *(uint32_t*)((char*)Chi + g0 * 2) = h0;
                *(uint32_t*)((char*)Clo + g0 * 2) = l0;
                *(uint32_t*)((char*)Chi + g1 * 2) = h1;
                *(uint32_t*)((char*)Clo + g1 * 2) = l1;
            }
        }
    }
}

// ---------------------------------------------------------------------------
// fgate2 + x-split fusion
// ---------------------------------------------------------------------------
__global__ __launch_bounds__(256) void fgate2_kernel(
    const float* __restrict__ x, const float* __restrict__ Wf,
    const float* __restrict__ delta, float* __restrict__ lf,
    __nv_bfloat16* __restrict__ xhi, __nv_bfloat16* __restrict__ xlo)
{
    extern __shared__ float sw[];  // 16*1024 floats = 64KB
    int tid = threadIdx.x, lane = tid & 31, warp = tid >> 5;
    for (int i = tid; i < 4096; i += 256)
        ((float4*)sw)[i] = ((const float4*)Wf)[i];
    __syncthreads();

    int row = blockIdx.x * 8 + warp;
    const float4* xp = (const float4*)(x + (size_t)row * 1024);
    float4 xr[8];
#pragma unroll
    for (int j = 0; j < 8; j++) xr[j] = xp[lane + 32 * j];

    uint2* xh2 = (uint2*)(xhi + (size_t)row * 1024);
    uint2* xl2 = (uint2*)(xlo + (size_t)row * 1024);
#pragma unroll
    for (int j = 0; j < 8; j++) {
        uint32_t h0, l0, h1, l1;
        split2(xr[j].x, xr[j].y, h0, l0);
        split2(xr[j].z, xr[j].w, h1, l1);
        xh2[lane + 32 * j] = make_uint2(h0, h1);
        xl2[lane + 32 * j] = make_uint2(l0, l1);
    }

    int b = row >> 13, n = row & 8191;
#pragma unroll 1
    for (int h = 0; h < NHEAD; h++) {
        const float4* wp = (const float4*)(sw + h * 1024);
        float s = 0.f;
#pragma unroll
        for (int j = 0; j < 8; j++) {
            float4 w4 = wp[lane + 32 * j];
            s += xr[j].x * w4.x + xr[j].y * w4.y + xr[j].z * w4.z + xr[j].w * w4.w;
        }
#pragma unroll
        for (int off = 16; off; off >>= 1) s += __shfl_xor_sync(0xffffffffu, s, off);
        if (lane == 0) {
            float z = s + delta[h];
            lf[((size_t)(b * NHEAD + h)) * SEQ + n] =
                fminf(z, 0.f) - log1pf(expf(-fabsf(z)));
        }
    }
}

// ---------------------------------------------------------------------------
// Pass A tensorized, cp.async edition. lf is already per-chunk cumsum.
// ---------------------------------------------------------------------------
__global__ __launch_bounds__(256) void scan_intra_mma(
    const __nv_bfloat16* __restrict__ qhi, const __nv_bfloat16* __restrict__ qlo,
    const __nv_bfloat16* __restrict__ khi, const __nv_bfloat16* __restrict__ klo,
    const __nv_bfloat16* __restrict__ vhi, const __nv_bfloat16* __restrict__ vlo,
    const float* __restrict__ lf, float* __restrict__ o, float* __restrict__ dS)
{
    extern __shared__ __align__(16) char sm[];
    const uint32_t sb = smem_u32(sm);
    float* sE  = (float*)(sm + OFF_SE);
    float* sEi = (float*)(sm + OFF_SEI);

    const int chunk = blockIdx.x, bh = blockIdx.y;
    const int b = bh >> 4, h = bh & 15;
    const int tid = threadIdx.x, lane = tid & 31, wid = tid >> 5;
    const size_t rowbase = (size_t)(b * SEQ + chunk * CHUNK);
    const size_t base = rowbase * DDIM + h * HDIM;        // fp32-element offset for o
    const size_t bytebase = rowbase * 2048 + h * 128;     // byte offset into bf16 [row][1024]

    // ---- cp.async: q,k (d-major, pitch P1) and v staging (row-major) ----
    {
        const int r = tid >> 3, c16 = (tid & 7) * 16;
#pragma unroll
        for (int i = 0; i < 4; i++) {
            int rr = r + i * 32;
            size_t src = bytebase + (size_t)rr * 2048 + c16;
            cp16(sb + OFF_QHI + rr * P1 + c16, (const char*)qhi + src);
            cp16(sb + OFF_QLO + rr * P1 + c16, (const char*)qlo + src);
            cp16(sb + OFF_KHI + rr * P1 + c16, (const char*)khi + src);
            cp16(sb + OFF_KLO + rr * P1 + c16, (const char*)klo + src);
            cp16(sb + OFF_VSH + rr * PS + c16, (const char*)vhi + src);
            cp16(sb + OFF_VSL + rr * PS + c16, (const char*)vlo + src);
        }
        asm volatile("cp.async.commit_group;" ::: "memory");
    }

    // gates (lf already cumsum) — overlapped with cp.async
    if (tid < 128) {
        float l = lf[(size_t)bh * SEQ + (size_t)chunk * CHUNK + tid];
        sE[tid]  = expf(l);
        sEi[tid] = expf(-l);
    }
    asm volatile("cp.async.wait_group 0;" ::: "memory");
    __syncthreads();

    // ---- build vT hi/lo (rows d, j-contig) from staging via byte_perm ----
#pragma unroll
    for (int i = 0; i < 4; i++) {
        int idx = tid + i * 256;
        int jp = idx >> 4, d4 = (idx & 15) * 4, j2 = jp * 2;
        uint2 a = *(uint2*)(sm + OFF_VSH + (j2 + 0) * PS + d4 * 2);
        uint2 c = *(uint2*)(sm + OFF_VSH + (j2 + 1) * PS + d4 * 2);
        *(uint32_t*)(sm + OFF_VTHI + (d4 + 0) * P2 + j2 * 2) = __byte_perm(a.x, c.x, 0x5410);
        *(uint32_t*)(sm + OFF_VTHI + (d4 + 1) * P2 + j2 * 2) = __byte_perm(a.x, c.x, 0x7632);
        *(uint32_t*)(sm + OFF_VTHI + (d4 + 2) * P2 + j2 * 2) = __byte_perm(a.y, c.y, 0x5410);
        *(uint32_t*)(sm + OFF_VTHI + (d4 + 3) * P2 + j2 * 2) = __byte_perm(a.y, c.y, 0x7632);
        uint2 al = *(uint2*)(sm + OFF_VSL + (j2 + 0) * PS + d4 * 2);
        uint2 cl = *(uint2*)(sm + OFF_VSL + (j2 + 1) * PS + d4 * 2);
        *(uint32_t*)(sm + OFF_VTLO + (d4 + 0) * P2 + j2 * 2) = __byte_perm(al.x, cl.x, 0x5410);
        *(uint32_t*)(sm + OFF_VTLO + (d4 + 1) * P2 + j2 * 2) = __byte_perm(al.x, cl.x, 0x7632);
        *(uint32_t*)(sm + OFF_VTLO + (d4 + 2) * P2 + j2 * 2) = __byte_perm(al.y, cl.y, 0x5410);
        *(uint32_t*)(sm + OFF_VTLO + (d4 + 3) * P2 + j2 * 2) = __byte_perm(al.y, cl.y, 0x7632);
    }
    __syncthreads();   // staging region about to be reused by kdT

    // ---- build kdT hi/lo (rows d, j-contig): kd[j][d] = (khi+klo)*exp(L-l_j) ----
    const float eL = sE[127];
#pragma unroll
    for (int i = 0; i < 4; i++) {
        int idx = tid + i * 256;
        int jp = idx >> 4, d4 = (idx & 15) * 4, j2 = jp * 2;
        float g0 = eL * sEi[j2], g1 = eL * sEi[j2 + 1];
        uint2 ah = *(uint2*)(sm + OFF_KHI + (j2 + 0) * P1 + d4 * 2);
        uint2 al = *(uint2*)(sm + OFF_KLO + (j2 + 0) * P1 + d4 * 2);
        uint2 bh_ = *(uint2*)(sm + OFF_KHI + (j2 + 1) * P1 + d4 * 2);
        uint2 bl_ = *(uint2*)(sm + OFF_KLO + (j2 + 1) * P1 + d4 * 2);
#pragma unroll
        for (int t = 0; t < 4; t++) {
            float v0 = (bf_at(ah, t) + bf_at(al, t)) * g0;
            float v1 = (bf_at(bh_, t) + bf_at(bl_, t)) * g1;
            uint32_t hw, lw;
            split2(v0, v1, hw, lw);
            *(uint32_t*)(sm + OFF_KDHI + (d4 + t) * P2 + j2 * 2) = hw;
            *(uint32_t*)(sm + OFF_KDLO + (d4 + t) * P2 + j2 * 2) = lw;
        }
    }

    const int lrow = ((lane >> 3) & 1) * 8 + (lane & 7);
    const int lcol8 = (lane >> 4) * 8;
    const int r0 = lane >> 2, c0 = (lane & 3) * 2;

    // ---- product 1: A = q k^T (128x128x64), then decay+mask+split -> smem ----
    {
        const int wm = wid & 1, wn = wid >> 1;
        float acc[4][4][4];
#pragma unroll
        for (int a0 = 0; a0 < 4; a0++)
#pragma unroll
            for (int a1 = 0; a1 < 4; a1++)
#pragma unroll
                for (int a2 = 0; a2 < 4; a2++) acc[a0][a1][a2] = 0.f;

        const uint32_t aqh = sb + OFF_QHI + (wm * 64) * P1;
        const uint32_t aql = sb + OFF_QLO + (wm * 64) * P1;
        const uint32_t bkh = sb + OFF_KHI + (wn * 32) * P1;
        const uint32_t bkl = sb + OFF_KLO + (wn * 32) * P1;
#pragma unroll
        for (int ks = 0; ks < 64; ks += 16) {
            const uint32_t loff = (uint32_t)lrow * P1 + (uint32_t)(ks + lcol8) * 2;
            uint32_t af[4][4], bhf[4][2], blf[4][2];
#pragma unroll
            for (int mf = 0; mf < 4; mf++) ldsm4(af[mf], aqh + mf * 16 * P1 + loff);
#pragma unroll
            for (int p = 0; p < 2; p++) {
                uint32_t t[4];
                ldsm4(t, bkh + p * 16 * P1 + loff);
                bhf[2 * p + 0][0] = t[0]; bhf[2 * p + 0][1] = t[2];
                bhf[2 * p + 1][0] = t[1]; bhf[2 * p + 1][1] = t[3];
            }
#pragma unroll
            for (int mf = 0; mf < 4; mf++)
#pragma unroll
                for (int nf = 0; nf < 4; nf++)
                    mma16816(acc[mf][nf], af[mf], bhf[nf][0], bhf[nf][1]);
#pragma unroll
            for (int p = 0; p < 2; p++) {
                uint32_t t[4];
                ldsm4(t, bkl + p * 16 * P1 + loff);
                blf[2 * p + 0][0] = t[0]; blf[2 * p + 0][1] = t[2];
                blf[2 * p + 1][0] = t[1]; blf[2 * p + 1][1] = t[3];
            }
#pragma unroll
            for (int mf = 0; mf < 4; mf++)
#pragma unroll
                for (int nf = 0; nf < 4; nf++)
                    mma16816(acc[mf][nf], af[mf], blf[nf][0], blf[nf][1]);
#pragma unroll
            for (int mf = 0; mf < 4; mf++) ldsm4(af[mf], aql + mf * 16 * P1 + loff);
#pragma unroll
            for (int mf = 0; mf < 4; mf++)
#pragma unroll
                for (int nf = 0; nf < 4; nf++)
                    mma16816(acc[mf][nf], af[mf], bhf[nf][0], bhf[nf][1]);
        }
        __syncthreads();   // all q/k reads + kdT build complete before A overlay

        // decay + causal mask + hi/lo split -> A smem (overlays q/k head)
#pragma unroll
        for (int mf = 0; mf < 4; mf++) {
            int i1 = wm * 64 + mf * 16 + r0;
            int i2 = i1 + 8;
            float e1 = sE[i1], e2 = sE[i2];
#pragma unroll
            for (int nf = 0; nf < 4; nf++) {
                int j0 = wn * 32 + nf * 8 + c0;
                float ej0 = sEi[j0], ej1 = sEi[j0 + 1];
                float v00 = (j0     <= i1) ? acc[mf][nf][0] * e1 * ej0 : 0.f;
                float v01 = (j0 + 1 <= i1) ? acc[mf][nf][1] * e1 * ej1 : 0.f;
                float v10 = (j0     <= i2) ? acc[mf][nf][2] * e2 * ej0 : 0.f;
                float v11 = (j0 + 1 <= i2) ? acc[mf][nf][3] * e2 * ej1 : 0.f;
                uint32_t hi0, lo0, hi1, lo1;
                split2(v00, v01, hi0, lo0);
                split2(v10, v11, hi1, lo1);
                *(uint32_t*)(sm + OFF_A   + i1 * P2 + j0 * 2) = hi0;
                *(uint32_t*)(sm + OFF_ALO + i1 * P2 + j0 * 2) = lo0;
                *(uint32_t*)(sm + OFF_A   + i2 * P2 + j0 * 2) = hi1;
                *(uint32_t*)(sm + OFF_ALO + i2 * P2 + j0 * 2) = lo1;
            }
        }
    }
    __syncthreads();

    // ---- product 2: o_intra = A @ v  (128x64x128) ----
    {
        const int wm = wid & 1, wn = wid >> 1;
        float acc[4][2][4];
#pragma unroll
        for (int a0 = 0; a0 < 4; a0++)
#pragma unroll
            for (int a1 = 0; a1 < 2; a1++)
#pragma unroll
                for (int a2 = 0; a2 < 4; a2++) acc[a0][a1][a2] = 0.f;

        const uint32_t aAh = sb + OFF_A    + (wm * 64) * P2;
        const uint32_t aAl = sb + OFF_ALO  + (wm * 64) * P2;
        const uint32_t bVh = sb + OFF_VTHI + (wn * 16) * P2;
        const uint32_t bVl = sb + OFF_VTLO + (wn * 16) * P2;
#pragma unroll
        for (int ks = 0; ks < 128; ks += 16) {
            const uint32_t loff = (uint32_t)lrow * P2 + (uint32_t)(ks + lcol8) * 2;
            uint32_t af[4][4], bhf[2][2], blf[2][2];
#pragma unroll
            for (int mf = 0; mf < 4; mf++) ldsm4(af[mf], aAh + mf * 16 * P2 + loff);
            {
                uint32_t t[4];
                ldsm4(t, bVh + loff);
                bhf[0][0] = t[0]; bhf[0][1] = t[2];
                bhf[1][0] = t[1]; bhf[1][1] = t[3];
            }
#pragma unroll
            for (int mf = 0; mf < 4; mf++)
#pragma unroll
                for (int nf = 0; nf < 2; nf++)
                    mma16816(acc[mf][nf], af[mf], bhf[nf][0], bhf[nf][1]);
            {
                uint32_t t[4];
                ldsm4(t, bVl + loff);
                blf[0][0] = t[0]; blf[0][1] = t[2];
                blf[1][0] = t[1]; blf[1][1] = t[3];
            }
#pragma unroll
            for (int mf = 0; mf < 4; mf++)
#pragma unroll
                for (int nf = 0; nf < 2; nf++)
                    mma16816(acc[mf][nf], af[mf], blf[nf][0], blf[nf][1]);
#pragma unroll
            for (int mf = 0; mf < 4; mf++) ldsm4(af[mf], aAl + mf * 16 * P2 + loff);
#pragma unroll
            for (int mf = 0; mf < 4; mf++)
#pragma unroll
                for (int nf = 0; nf < 2; nf++)
                    mma16816(acc[mf][nf], af[mf], bhf[nf][0], bhf[nf][1]);
        }
#pragma unroll
        for (int mf = 0; mf < 4; mf++) {
            int i1 = wm * 64 + mf * 16 + r0;
#pragma unroll
            for (int nf = 0; nf < 2; nf++) {
                int d0 = wn * 16 + nf * 8 + c0;
                *(float2*)(o + base + (size_t)i1 * DDIM + d0) =
                    make_float2(acc[mf][nf][0], acc[mf][nf][1]);
                *(float2*)(o + base + (size_t)(i1 + 8) * DDIM + d0) =
                    make_float2(acc[mf][nf][2], acc[mf][nf][3]);
            }
        }
    }

    // ---- product 3: dS = kd^T @ v  (64x64x128) ----
    {
        const int wm3 = wid & 3, wn3 = wid >> 2;
        float acc[4][4];
#pragma unroll
        for (int a0 = 0; a0 < 4; a0++)
#pragma unroll
            for (int a2 = 0; a2 < 4; a2++) acc[a0][a2] = 0.f;

        const uint32_t aKh = sb + OFF_KDHI + (wm3 * 16) * P2;
        const uint32_t aKl = sb + OFF_KDLO + (wm3 * 16) * P2;
        const uint32_t bVh = sb + OFF_VTHI + (wn3 * 32) * P2;
        const uint32_t bVl = sb + OFF_VTLO + (wn3 * 32) * P2;
#pragma unroll
        for (int ks = 0; ks < 128; ks += 16) {
            const uint32_t loff = (uint32_t)lrow * P2 + (uint32_t)(ks + lcol8) * 2;
            uint32_t af[4], afl[4], bhf[4][2], blf[4][2];
            ldsm4(af, aKh + loff);
#pragma unroll
            for (int p = 0; p < 2; p++) {
                uint32_t t[4];
                ldsm4(t, bVh + p * 16 * P2 + loff);
                bhf[2 * p + 0][0] = t[0]; bhf[2 * p + 0][1] = t[2];
                bhf[2 * p + 1][0] = t[1]; bhf[2 * p + 1][1] = t[3];
            }
#pragma unroll
            for (int nf = 0; nf < 4; nf++)
                mma16816(acc[nf], af, bhf[nf][0], bhf[nf][1]);
#pragma unroll
            for (int p = 0; p < 2; p++) {
                uint32_t t[4];
                ldsm4(t, bVl + p * 16 * P2 + loff);
                blf[2 * p + 0][0] = t[0]; blf[2 * p + 0][1] = t[2];
                blf[2 * p + 1][0] = t[1]; blf[2 * p + 1][1] = t[3];
            }
#pragma unroll
            for (int nf = 0; nf < 4; nf++)
                mma16816(acc[nf], af, blf[nf][0], blf[nf][1]);
            ldsm4(afl, aKl + loff);
#pragma unroll
            for (int nf = 0; nf < 4; nf++)
                mma16816(acc[nf], afl, bhf[nf][0], bhf[nf][1]);
        }
        size_t sb2 = ((size_t)bh * NCHUNK + chunk) * (HDIM * HDIM);
        int d1 = wm3 * 16 + r0;
#pragma unroll
        for (int nf = 0; nf < 4; nf++) {
            int e0 = wn3 * 32 + nf * 8 + c0;
            *(float2*)(dS + sb2 + (size_t)d1 * HDIM + e0) = make_float2(acc[nf][0], acc[nf][1]);
            *(float2*)(dS + sb2 + (size_t)(d1 + 8) * HDIM + e0) = make_float2(acc[nf][2], acc[nf][3]);
        }
    }
}

// ---------------------------------------------------------------------------
// Pass B: sequential 64-step state scan; grid (NBH, 8), 512 elems per block.
// ---------------------------------------------------------------------------
__global__ void scan_state_kernel(const float* __restrict__ dS, const float* __restrict__ lf,
                                  float* __restrict__ Sin)
{
    int bh = blockIdx.x, tid = threadIdx.x;
    int seg = blockIdx.y * 512;
    float S[2] = {0.f, 0.f};
    for (int chunk = 0; chunk < NCHUNK; chunk++) {
        size_t base = ((size_t)bh * NCHUNK + chunk) * (HDIM * HDIM) + seg;
        float eL = expf(lf[(size_t)bh * SEQ + chunk * CHUNK + (CHUNK - 1)]);
#pragma unroll
        for (int j = 0; j < 2; j++) {
            int idx = tid + j * 256;
            Sin[base + idx] = S[j];
            S[j] = eL * S[j] + dS[base + idx];
        }
    }
}

// ---------------------------------------------------------------------------
// Pass C tensorized, cp.async q: o += exp(l_i) * (q @ S_in)
// ---------------------------------------------------------------------------
__global__ __launch_bounds__(256) void scan_inter_mma(
    const __nv_bfloat16* __restrict__ qhi, const __nv_bfloat16* __restrict__ qlo,
    const float* __restrict__ lf, const float* __restrict__ Sin, float* __restrict__ o)
{
    extern __shared__ __align__(16) char sm[];
    const uint32_t sb = smem_u32(sm);
    float* slf = (float*)(sm + IOFF_LF);

    const int chunk = blockIdx.x, bh = blockIdx.y;
    const int b = bh >> 4, h = bh & 15;
    const int tid = threadIdx.x, lane = tid & 31, wid = tid >> 5;
    const size_t rowbase = (size_t)(b * SEQ + chunk * CHUNK);
    const size_t base = rowbase * DDIM + h * HDIM;
    const size_t bytebase = rowbase * 2048 + h * 128;

    // cp.async q hi/lo
    {
        const int r = tid >> 3, c16 = (tid & 7) * 16;
#pragma unroll
        for (int i = 0; i < 4; i++) {
            int rr = r + i * 32;
            size_t src = bytebase + (size_t)rr * 2048 + c16;
            cp16(sb + IOFF_QHI + rr * P1 + c16, (const char*)qhi + src);
            cp16(sb + IOFF_QLO + rr * P1 + c16, (const char*)qlo + src);
        }
        asm volatile("cp.async.commit_group;" ::: "memory");
    }

    // SinT hi/lo build (rows e, d-contig) — independent of cp.async
    size_t sb2 = ((size_t)bh * NCHUNK + chunk) * (HDIM * HDIM);
#pragma unroll
    for (int i = 0; i < 8; i++) {
        int idx = tid + i * 256;
        int dp = idx >> 6, e = idx & 63, d = dp * 2;
        float s0 = Sin[sb2 + (size_t)d * HDIM + e];
        float s1 = Sin[sb2 + (size_t)(d + 1) * HDIM + e];
        uint32_t hw, lw;
        split2(s0, s1, hw, lw);
        *(uint32_t*)(sm + IOFF_STH + e * P1 + d * 2) = hw;
        *(uint32_t*)(sm + IOFF_STL + e * P1 + d * 2) = lw;
    }
    if (tid < 128) slf[tid] = lf[(size_t)bh * SEQ + (size_t)chunk * CHUNK + tid];
    asm volatile("cp.async.wait_group 0;" ::: "memory");
    __syncthreads();

    const int lrow = ((lane >> 3) & 1) * 8 + (lane & 7);
    const int lcol8 = (lane >> 4) * 8;
    const int r0 = lane >> 2, c0 = (lane & 3) * 2;
    const int wm = wid & 1, wn = wid >> 1;

    float acc[4][2][4];
#pragma unroll
    for (int a0 = 0; a0 < 4; a0++)
#pragma unroll
        for (int a1 = 0; a1 < 2; a1++)
#pragma unroll
            for (int a2 = 0; a2 < 4; a2++) acc[a0][a1][a2] = 0.f;

    const uint32_t aQh = sb + IOFF_QHI + (wm * 64) * P1;
    const uint32_t aQl = sb + IOFF_QLO + (wm * 64) * P1;
    const uint32_t bSh = sb + IOFF_STH + (wn * 16) * P1;
    const uint32_t bSl = sb + IOFF_STL + (wn * 16) * P1;
#pragma unroll
    for (int ks = 0; ks < 64; ks += 16) {
        const uint32_t loff = (uint32_t)lrow * P1 + (uint32_t)(ks + lcol8) * 2;
        uint32_t af[4][4], bhf[2][2], blf[2][2];
#pragma unroll
        for (int mf = 0; mf < 4; mf++) ldsm4(af[mf], aQh + mf * 16 * P1 + loff);
        {
            uint32_t t[4];
            ldsm4(t, bSh + loff);
            bhf[0][0] = t[0]; bhf[0][1] = t[2];
            bhf[1][0] = t[1]; bhf[1][1] = t[3];
        }
#pragma unroll
        for (int mf = 0; mf < 4; mf++)
#pragma unroll
            for (int nf = 0; nf < 2; nf++)
                mma16816(acc[mf][nf], af[mf], bhf[nf][0], bhf[nf][1]);
        {
            uint32_t t[4];
            ldsm4(t, bSl + loff);
            blf[0][0] = t[0]; blf[0][1] = t[2];
            blf[1][0] = t[1]; blf[1][1] = t[3];
        }
#pragma unroll
        for (int mf = 0; mf < 4; mf++)
#pragma unroll
            for (int nf = 0; nf < 2; nf++)
                mma16816(acc[mf][nf], af[mf], blf[nf][0], blf[nf][1]);
#pragma unroll
        for (int mf = 0; mf < 4; mf++) ldsm4(af[mf], aQl + mf * 16 * P1 + loff);
#pragma unroll
        for (int mf = 0; mf < 4; mf++)
#pragma unroll
            for (int nf = 0; nf < 2; nf++)
                mma16816(acc[mf][nf], af[mf], bhf[nf][0], bhf[nf][1]);
    }

#pragma unroll
    for (int mf = 0; mf < 4; mf++) {
        int i1 = wm * 64 + mf * 16 + r0;
        float e1 = expf(slf[i1]), e2 = expf(slf[i1 + 8]);
#pragma unroll
        for (int nf = 0; nf < 2; nf++) {
            int d0 = wn * 16 + nf * 8 + c0;
            float2* p1 = (float2*)(o + base + (size_t)i1 * DDIM + d0);
            float2 c1 = *p1;
            c1.x += e1 * acc[mf][nf][0];
            c1.y += e1 * acc[mf][nf][1];
            *p1 = c1;
            float2* p2 = (float2*)(o + base + (size_t)(i1 + 8) * DDIM + d0);
            float2 c2 = *p2;
            c2.x += e2 * acc[mf][nf][2];
            c2.y += e2 * acc[mf][nf][3];
            *p2 = c2;
        }
    }
}

// ---------------------------------------------------------------------------
// RMSNorm over last dim (1024); emits (hi, lo) bf16 directly for the Wo GEMM.
// ---------------------------------------------------------------------------
__global__ void rmsnorm_kernel(const float* __restrict__ o, const float* __restrict__ w,
                               __nv_bfloat16* __restrict__ ohi, __nv_bfloat16* __restrict__ olo)
{
    __shared__ float red[8];
    size_t base = (size_t)blockIdx.x * 1024;
    int tid = threadIdx.x;
    float vals[4];
    float ss = 0.f;
#pragma unroll
    for (int j = 0; j < 4; j++) {
        float t = o[base + tid + j * 256];
        vals[j] = t;
        ss += t * t;
    }
#pragma unroll
    for (int off = 16; off; off >>= 1) ss += __shfl_xor_sync(0xffffffffu, ss, off);
    if ((tid & 31) == 0) red[tid >> 5] = ss;
    __syncthreads();
    float tot = red[0] + red[1] + red[2] + red[3] + red[4] + red[5] + red[6] + red[7];
    float scale = rsqrtf(tot * (1.f / 1024.f) + 1e-6f);
#pragma unroll
    for (int j = 0; j < 4; j++) {
        int c = tid + j * 256;
        float t = vals[j] * scale * w[c];
        __nv_bfloat16 h = __float2bfloat16(t);
        ohi[base + c] = h;
        olo[base + c] = __float2bfloat16(t - __bfloat162float(h));
    }
}

// ---------------------------------------------------------------------------
extern "C" void kernel_launch(void* const* d_in, const int* in_sizes, int n_in,
                              void* d_out, int out_size)
{
    const float* x  = (const float*)d_in[0];
    const float* Wq = (const float*)d_in[1];
    const float* Wk = (const float*)d_in[2];
    const float* Wv = (const float*)d_in[3];
    const float* Wo = (const float*)d_in[4];
    const float* Wf = (const float*)d_in[5];
    const float* dl = (const float*)d_in[6];
    const float* nw = (const float*)d_in[7];
    float* out = (float*)d_out;

    float *o, *lf, *dS, *Sin;
    cudaGetSymbolAddress((void**)&o,   g_o);
    cudaGetSymbolAddress((void**)&lf,  g_lf);
    cudaGetSymbolAddress((void**)&dS,  g_dS);
    cudaGetSymbolAddress((void**)&Sin, g_Sin);

    __nv_bfloat16 *xhi, *xlo, *ohi, *olo;
    __nv_bfloat16 *qhi, *qlo, *khi, *klo, *vhi, *vlo;
    __nv_bfloat16 *wqh, *wql, *wkh, *wkl, *wvh, *wvl, *woh, *wol;
    cudaGetSymbolAddress((void**)&xhi, g_xhi);
    cudaGetSymbolAddress((void**)&xlo, g_xlo);
    cudaGetSymbolAddress((void**)&ohi, g_ohi);
    cudaGetSymbolAddress((void**)&olo, g_olo);
    cudaGetSymbolAddress((void**)&qhi, g_qhi);
    cudaGetSymbolAddress((void**)&qlo, g_qlo);
    cudaGetSymbolAddress((void**)&khi, g_khi);
    cudaGetSymbolAddress((void**)&klo, g_klo);
    cudaGetSymbolAddress((void**)&vhi, g_vhi);
    cudaGetSymbolAddress((void**)&vlo, g_vlo);
    cudaGetSymbolAddress((void**)&wqh, g_wqhi);
    cudaGetSymbolAddress((void**)&wql, g_wqlo);
    cudaGetSymbolAddress((void**)&wkh, g_wkhi);
    cudaGetSymbolAddress((void**)&wkl, g_wklo);
    cudaGetSymbolAddress((void**)&wvh, g_wvhi);
    cudaGetSymbolAddress((void**)&wvl, g_wvlo);
    cudaGetSymbolAddress((void**)&woh, g_wohi);
    cudaGetSymbolAddress((void**)&wol, g_wolo);

    const int SMEM_GEMM = 2 * BUFB;         // 81920 B
    const int SMEM_FG   = 16 * 1024 * 4;    // 65536 B
    cudaFuncSetAttribute(gemm_mma, cudaFuncAttributeMaxDynamicSharedMemorySize, SMEM_GEMM);
    cudaFuncSetAttribute(fgate2_kernel, cudaFuncAttributeMaxDynamicSharedMemorySize, SMEM_FG);
    cudaFuncSetAttribute(scan_intra_mma, cudaFuncAttributeMaxDynamicSharedMemorySize, SMEM_INTRA_MMA);
    cudaFuncSetAttribute(scan_inter_mma, cudaFuncAttributeMaxDynamicSharedMemorySize, SMEM_INTER_MMA);

    const int N4W = DDIM * DDIM / 4;

    split_kernel<<<N4W / 256, 256>>>(Wq, wqh, wql, N4W);
    split_kernel<<<N4W / 256, 256>>>(Wk, wkh, wkl, N4W);
    split_kernel<<<N4W / 256, 256>>>(Wv, wvh, wvl, N4W);
    split_kernel<<<N4W / 256, 256>>>(Wo, woh, wol, N4W);
    fgate2_kernel<<<MROWS / 8, 256, SMEM_FG>>>(x, Wf, dl, lf, xhi, xlo);
    cumsum_kernel<<<NBH * NCHUNK, 128>>>(lf);

    dim3 gg(DDIM / GTN, MROWS / GTM);   // (8, 256)
    gemm_mma<<<gg, 256, SMEM_GEMM>>>(xhi, xlo, wqh, wql, nullptr, qhi, qlo, 1, 1);
    gemm_mma<<<gg, 256, SMEM_GEMM>>>(xhi, xlo, wkh, wkl, nullptr, khi, klo, 1, 1);
    gemm_mma<<<gg, 256, SMEM_GEMM>>>(xhi, xlo, wvh, wvl, nullptr, vhi, vlo, 0, 1);

    scan_intra_mma<<<dim3(NCHUNK, NBH), 256, SMEM_INTRA_MMA>>>(qhi, qlo, khi, klo, vhi, vlo,
                                                               lf, o, dS);
    scan_state_kernel<<<dim3(NBH, 8), 256>>>(dS, lf, Sin);
    scan_inter_mma<<<dim3(NCHUNK, NBH), 256, SMEM_INTER_MMA>>>(qhi, qlo, lf, Sin, o);
    rmsnorm_kernel<<<MROWS, 256>>>(o, nw, ohi, olo);

    gemm_mma<<<gg, 256, SMEM_GEMM>>>(ohi, olo, woh, wol, out, nullptr, nullptr, 0, 0);
}